// round 2
// baseline (speedup 1.0000x reference)
#include <cuda_runtime.h>
#include <cooperative_groups.h>
#include <math.h>

namespace cg = cooperative_groups;

#define TT 512
#define BB 64
#define HH 256
#define NK 32

// ---------------- scratch (device globals; no allocations allowed) ----------------
__device__ float g_gx[2][TT][BB][4 * HH];   // input projections, both directions (268 MB)
__device__ float g_h[2][TT][BB][HH];        // hidden states fwd/bwd (67 MB)
__device__ float g_scores[BB][TT][NK];      // emission scores (4 MB)
__device__ float g_loss[BB];                // per-batch (total - true)

// =================================================================================
// Kernel 1: embedding gather + input projection GEMM (both directions fused)
//   g_gx[dir][t][b][j] = sum_k emb[x[b,t],k] * w_ih[dir][j,k] + b[dir][j]
// Tiles: BM=64 (= all 64 batch rows of one t), BN=64, BK=16; 256 thr, 4x4 microtile.
// =================================================================================
__global__ __launch_bounds__(256) void proj_kernel(
    const int* __restrict__ x, const float* __restrict__ emb,
    const float* __restrict__ w_f, const float* __restrict__ bf_,
    const float* __restrict__ w_b, const float* __restrict__ bb_)
{
    __shared__ float As[16 * 64];
    __shared__ float Bs[16 * 64];
    __shared__ int sidx[64];

    const int mt   = blockIdx.x;        // time index t (BM == B == 64)
    const int n0   = blockIdx.y * 64;   // global output column tile (0..2047)
    const int dir  = n0 >> 10;
    const int col0 = n0 & 1023;
    const float* __restrict__ W    = dir ? w_b : w_f;
    const float* __restrict__ bias = dir ? bb_ : bf_;

    const int tid = threadIdx.x;
    if (tid < 64) sidx[tid] = x[tid * TT + mt];
    __syncthreads();

    const int lm  = tid >> 2;          // 0..63  (row for A-load / col for B-load)
    const int kq  = (tid & 3) << 2;    // k sub-offset (float4)
    const int ty4 = (tid >> 4) << 2;   // micro-tile row base
    const int tx4 = (tid & 15) << 2;   // micro-tile col base

    float acc[4][4] = {};

    for (int k0 = 0; k0 < 256; k0 += 16) {
        float4 av = *(const float4*)&emb[(size_t)sidx[lm] * 256 + k0 + kq];
        float4 bv = *(const float4*)&W[(size_t)(col0 + lm) * 256 + k0 + kq];
        As[(kq + 0) * 64 + lm] = av.x; As[(kq + 1) * 64 + lm] = av.y;
        As[(kq + 2) * 64 + lm] = av.z; As[(kq + 3) * 64 + lm] = av.w;
        Bs[(kq + 0) * 64 + lm] = bv.x; Bs[(kq + 1) * 64 + lm] = bv.y;
        Bs[(kq + 2) * 64 + lm] = bv.z; Bs[(kq + 3) * 64 + lm] = bv.w;
        __syncthreads();

        #pragma unroll
        for (int kk = 0; kk < 16; kk++) {
            float4 a = *(const float4*)&As[kk * 64 + ty4];
            float4 b = *(const float4*)&Bs[kk * 64 + tx4];
            acc[0][0] = fmaf(a.x, b.x, acc[0][0]); acc[0][1] = fmaf(a.x, b.y, acc[0][1]);
            acc[0][2] = fmaf(a.x, b.z, acc[0][2]); acc[0][3] = fmaf(a.x, b.w, acc[0][3]);
            acc[1][0] = fmaf(a.y, b.x, acc[1][0]); acc[1][1] = fmaf(a.y, b.y, acc[1][1]);
            acc[1][2] = fmaf(a.y, b.z, acc[1][2]); acc[1][3] = fmaf(a.y, b.w, acc[1][3]);
            acc[2][0] = fmaf(a.z, b.x, acc[2][0]); acc[2][1] = fmaf(a.z, b.y, acc[2][1]);
            acc[2][2] = fmaf(a.z, b.z, acc[2][2]); acc[2][3] = fmaf(a.z, b.w, acc[2][3]);
            acc[3][0] = fmaf(a.w, b.x, acc[3][0]); acc[3][1] = fmaf(a.w, b.y, acc[3][1]);
            acc[3][2] = fmaf(a.w, b.z, acc[3][2]); acc[3][3] = fmaf(a.w, b.w, acc[3][3]);
        }
        __syncthreads();
    }

    #pragma unroll
    for (int i = 0; i < 4; i++) {
        float4 o;
        o.x = acc[i][0] + bias[col0 + tx4 + 0];
        o.y = acc[i][1] + bias[col0 + tx4 + 1];
        o.z = acc[i][2] + bias[col0 + tx4 + 2];
        o.w = acc[i][3] + bias[col0 + tx4 + 3];
        *(float4*)&g_gx[dir][mt][ty4 + i][col0 + tx4] = o;
    }
}

// =================================================================================
// Kernel 2: bidirectional LSTM recurrence.
// Cluster of 8 CTAs = one (direction, batch-group-of-8). Each CTA owns 32 hidden
// units: its 128 W_hh rows (4 gates x 32) live in SMEM as fp32 [k][r] (128 KB).
// h (double-buffered [2][256][8]) is exchanged via DSMEM each step + cluster.sync.
// Grid = 2 dirs * 8 groups * 8 ranks = 128 CTAs, 256 threads.
// =================================================================================
#define REC_SMEM_FLOATS (256 * 128 + 2 * 256 * 8 + 128 * 9)
#define REC_SMEM_BYTES  (REC_SMEM_FLOATS * 4)

__global__ __launch_bounds__(256) __cluster_dims__(8, 1, 1) void lstm_rec_kernel(
    const float* __restrict__ w_hh_f, const float* __restrict__ w_hh_b)
{
    extern __shared__ float smem[];
    float* sW = smem;                        // [256][128]  (k-major, conflict-free reads)
    float* sH = smem + 256 * 128;            // [2][256][8] (buf, k, batch)
    float* sZ = sH + 2 * 256 * 8;            // [128][9]    (padded to kill conflicts)

    cg::cluster_group cluster = cg::this_cluster();
    const unsigned rank = cluster.block_rank();      // 0..7 -> hidden-unit slice
    const int bx  = blockIdx.x;
    const int cid = bx >> 3;                         // 0..15
    const int d   = cid >> 3;                        // direction
    const int b0  = (cid & 7) * 8;                   // batch group base
    const int tid = threadIdx.x;

    const float* __restrict__ Wg = d ? w_hh_b : w_hh_f;

    // Load our 128 W rows into SMEM (transposed to [k][r]).
    for (int i = tid; i < 128 * 256; i += 256) {
        int r = i >> 8, k = i & 255;
        int gate = r >> 5, u = r & 31;
        int j = gate * 256 + rank * 32 + u;
        sW[k * 128 + r] = Wg[(size_t)j * 256 + k];
    }
    // Zero h buffer 0.
    for (int i = tid; i < 256 * 8; i += 256) sH[i] = 0.0f;
    __syncthreads();
    cluster.sync();

    // GEMM-phase mapping: 256 threads = 128 rows x 2 batch-halves.
    const int r    = tid & 127;
    const int bh   = tid >> 7;                 // 0 or 1 -> batches bh*4 .. bh*4+3
    const int gate = r >> 5, u = r & 31;
    const int j    = gate * 256 + rank * 32 + u;
    // Gate-phase mapping: (batch gb, unit gu).
    const int gb = tid >> 5, gu = tid & 31;
    const int hj = rank * 32 + gu;             // owned hidden index

    float c = 0.0f;
    int p = 0;

    for (int s = 0; s < TT; s++) {
        const int t = d ? (TT - 1 - s) : s;

        const float* __restrict__ gxp = &g_gx[d][t][b0 + bh * 4][j];
        float gx0 = gxp[0], gx1 = gxp[1024], gx2 = gxp[2048], gx3 = gxp[3072];

        float a0 = 0.f, a1 = 0.f, a2 = 0.f, a3 = 0.f;
        const float* hb = sH + p * 2048 + bh * 4;
        #pragma unroll 8
        for (int k = 0; k < 256; k++) {
            float  w  = sW[k * 128 + r];
            float4 h4 = *(const float4*)(hb + k * 8);
            a0 = fmaf(w, h4.x, a0); a1 = fmaf(w, h4.y, a1);
            a2 = fmaf(w, h4.z, a2); a3 = fmaf(w, h4.w, a3);
        }
        sZ[r * 9 + bh * 4 + 0] = a0 + gx0;
        sZ[r * 9 + bh * 4 + 1] = a1 + gx1;
        sZ[r * 9 + bh * 4 + 2] = a2 + gx2;
        sZ[r * 9 + bh * 4 + 3] = a3 + gx3;
        __syncthreads();

        // Gates: z order along 4H is [i | f | g | o].
        float zi = sZ[(gu)      * 9 + gb];
        float zf = sZ[(32 + gu) * 9 + gb];
        float zg = sZ[(64 + gu) * 9 + gb];
        float zo = sZ[(96 + gu) * 9 + gb];
        float si = 1.0f / (1.0f + __expf(-zi));
        float sf = 1.0f / (1.0f + __expf(-zf));
        float so = 1.0f / (1.0f + __expf(-zo));
        c = sf * c + si * tanhf(zg);
        float h = so * tanhf(c);

        g_h[d][t][b0 + gb][hj] = h;

        const int pn  = p ^ 1;
        const int off = pn * 2048 + hj * 8 + gb;
        #pragma unroll
        for (int pr = 0; pr < 8; pr++) {
            float* dst = cluster.map_shared_rank(sH, pr);
            dst[off] = h;
        }
        cluster.sync();
        p = pn;
    }
}

// =================================================================================
// Kernel 3: scores[b,t,k] = concat(h_f, h_b)[b,t] . w_fc[k] + b_fc[k]
// 64 blocks (one per batch), 8 warps stride over t, lane = k. w_fc transposed in SMEM.
// =================================================================================
__global__ __launch_bounds__(256) void scores_kernel(
    const float* __restrict__ w_fc, const float* __restrict__ b_fc)
{
    extern __shared__ float sWT[];            // [512][32] = w_fc^T
    const int b   = blockIdx.x;
    const int tid = threadIdx.x;
    for (int i = tid; i < 512 * 32; i += 256) {
        int dd = i & 511, k = i >> 9;
        sWT[dd * 32 + k] = w_fc[k * 512 + dd];
    }
    __syncthreads();

    const int wi = tid >> 5, k = tid & 31;
    const float bias = b_fc[k];
    for (int t = wi; t < TT; t += 8) {
        const float* __restrict__ hf = &g_h[0][t][b][0];
        const float* __restrict__ hb = &g_h[1][t][b][0];
        float acc = bias;
        #pragma unroll 4
        for (int dd = 0; dd < 256; dd++) {
            acc = fmaf(hf[dd], sWT[dd * 32 + k], acc);
            acc = fmaf(hb[dd], sWT[(256 + dd) * 32 + k], acc);
        }
        g_scores[b][t][k] = acc;
    }
}

// =================================================================================
// Kernel 4: CRF — gold-path score + forward algorithm (stable logsumexp).
// One warp per batch element; lane j = CRF state. mask is a contiguous prefix,
// so alpha-freeze under mask == stopping at len.
// =================================================================================
__global__ __launch_bounds__(32) void crf_kernel(
    const int* __restrict__ tags, const int* __restrict__ mask,
    const float* __restrict__ trans)
{
    __shared__ float sT[32 * 32];
    __shared__ float sA[32];
    const int b = blockIdx.x;
    const int j = threadIdx.x;

    for (int i = j; i < 1024; i += 32) sT[i] = trans[i];
    __syncwarp();

    // sequence length
    int len = 0;
    for (int t = j; t < TT; t += 32) len += mask[b * TT + t];
    #pragma unroll
    for (int o = 16; o; o >>= 1) len += __shfl_xor_sync(0xffffffffu, len, o);

    // gold path score
    const int* __restrict__ tg = tags + b * TT;
    float body = 0.0f;
    for (int t = 1 + j; t < len; t += 32) {
        int tp = tg[t - 1], tc = tg[t];
        body += sT[tp * 32 + tc] + g_scores[b][t][tc];
    }
    #pragma unroll
    for (int o = 16; o; o >>= 1) body += __shfl_xor_sync(0xffffffffu, body, o);
    const int t0 = tg[0];
    const float truep = sT[30 * 32 + t0] + g_scores[b][0][t0] + body
                      + sT[tg[len - 1] * 32 + 31];

    // forward algorithm
    float alpha = sT[30 * 32 + j] + g_scores[b][0][j];
    sA[j] = alpha;
    __syncwarp();
    for (int t = 1; t < len; t++) {
        float m = -1e30f;
        #pragma unroll
        for (int i = 0; i < 32; i++) m = fmaxf(m, sA[i] + sT[i * 32 + j]);
        float s = 0.0f;
        #pragma unroll
        for (int i = 0; i < 32; i++) s += __expf(sA[i] + sT[i * 32 + j] - m);
        alpha = g_scores[b][t][j] + m + __logf(s);
        __syncwarp();
        sA[j] = alpha;
        __syncwarp();
    }

    float v = alpha + sT[j * 32 + 31];
    float m = v;
    #pragma unroll
    for (int o = 16; o; o >>= 1) m = fmaxf(m, __shfl_xor_sync(0xffffffffu, m, o));
    float e = __expf(v - m);
    #pragma unroll
    for (int o = 16; o; o >>= 1) e += __shfl_xor_sync(0xffffffffu, e, o);
    if (j == 0) g_loss[b] = (m + __logf(e)) - truep;   // total - true
}

// loss = -sum(true - total) = sum(total - true); fixed-order sum for determinism.
__global__ void finalize_kernel(float* __restrict__ out)
{
    if (threadIdx.x == 0) {
        float s = 0.0f;
        for (int b = 0; b < BB; b++) s += g_loss[b];
        out[0] = s;
    }
}

// =================================================================================
extern "C" void kernel_launch(void* const* d_in, const int* in_sizes, int n_in,
                              void* d_out, int out_size)
{
    const int*   x      = (const int*)  d_in[0];
    const int*   tags   = (const int*)  d_in[1];
    const int*   mask   = (const int*)  d_in[2];
    const float* emb    = (const float*)d_in[3];
    const float* w_ih_f = (const float*)d_in[4];
    const float* w_hh_f = (const float*)d_in[5];
    const float* b_f    = (const float*)d_in[6];
    const float* w_ih_b = (const float*)d_in[7];
    const float* w_hh_b = (const float*)d_in[8];
    const float* b_b    = (const float*)d_in[9];
    const float* w_fc   = (const float*)d_in[10];
    const float* b_fc   = (const float*)d_in[11];
    const float* trans  = (const float*)d_in[12];
    float* out = (float*)d_out;

    cudaFuncSetAttribute(lstm_rec_kernel,
                         cudaFuncAttributeMaxDynamicSharedMemorySize, REC_SMEM_BYTES);
    cudaFuncSetAttribute(scores_kernel,
                         cudaFuncAttributeMaxDynamicSharedMemorySize, 512 * 32 * 4);

    proj_kernel<<<dim3(512, 32), 256>>>(x, emb, w_ih_f, b_f, w_ih_b, b_b);
    lstm_rec_kernel<<<128, 256, REC_SMEM_BYTES>>>(w_hh_f, w_hh_b);
    scores_kernel<<<64, 256, 512 * 32 * 4>>>(w_fc, b_fc);
    crf_kernel<<<64, 32>>>(tags, mask, trans);
    finalize_kernel<<<1, 32>>>(out);
}

// round 4
// speedup vs baseline: 1.0010x; 1.0010x over previous
#include <cuda_runtime.h>
#include <cooperative_groups.h>
#include <math.h>

namespace cg = cooperative_groups;

#define TT 512
#define BB 64
#define HH 256
#define NK 32

// ---------------- scratch (device globals; no allocations allowed) ----------------
__device__ float g_gx[2][TT][BB][4 * HH];   // input projections, both directions (268 MB)
__device__ float g_h[2][TT][BB][HH];        // hidden states fwd/bwd (67 MB)
__device__ float g_scores[BB][TT][NK];      // emission scores (4 MB)
__device__ float g_loss[BB];                // per-batch (total - true)

// =================================================================================
// Kernel 1: embedding gather + input projection GEMM (both directions fused)
//   g_gx[dir][t][b][j] = sum_k emb[x[b,t],k] * w_ih[dir][j,k] + b[dir][j]
// Tiles: BM=64 (= all 64 batch rows of one t), BN=64, BK=16; 256 thr, 4x4 microtile.
// =================================================================================
__global__ __launch_bounds__(256) void proj_kernel(
    const int* __restrict__ x, const float* __restrict__ emb,
    const float* __restrict__ w_f, const float* __restrict__ bf_,
    const float* __restrict__ w_b, const float* __restrict__ bb_)
{
    __shared__ float As[16 * 64];
    __shared__ float Bs[16 * 64];
    __shared__ int sidx[64];

    const int mt   = blockIdx.x;        // time index t (BM == B == 64)
    const int n0   = blockIdx.y * 64;   // global output column tile (0..2047)
    const int dir  = n0 >> 10;
    const int col0 = n0 & 1023;
    const float* __restrict__ W    = dir ? w_b : w_f;
    const float* __restrict__ bias = dir ? bb_ : bf_;

    const int tid = threadIdx.x;
    if (tid < 64) sidx[tid] = x[tid * TT + mt];
    __syncthreads();

    const int lm  = tid >> 2;          // 0..63  (row for A-load / col for B-load)
    const int kq  = (tid & 3) << 2;    // k sub-offset (float4)
    const int ty4 = (tid >> 4) << 2;   // micro-tile row base
    const int tx4 = (tid & 15) << 2;   // micro-tile col base

    float acc[4][4] = {};

    for (int k0 = 0; k0 < 256; k0 += 16) {
        float4 av = *(const float4*)&emb[(size_t)sidx[lm] * 256 + k0 + kq];
        float4 bv = *(const float4*)&W[(size_t)(col0 + lm) * 256 + k0 + kq];
        As[(kq + 0) * 64 + lm] = av.x; As[(kq + 1) * 64 + lm] = av.y;
        As[(kq + 2) * 64 + lm] = av.z; As[(kq + 3) * 64 + lm] = av.w;
        Bs[(kq + 0) * 64 + lm] = bv.x; Bs[(kq + 1) * 64 + lm] = bv.y;
        Bs[(kq + 2) * 64 + lm] = bv.z; Bs[(kq + 3) * 64 + lm] = bv.w;
        __syncthreads();

        #pragma unroll
        for (int kk = 0; kk < 16; kk++) {
            float4 a = *(const float4*)&As[kk * 64 + ty4];
            float4 b = *(const float4*)&Bs[kk * 64 + tx4];
            acc[0][0] = fmaf(a.x, b.x, acc[0][0]); acc[0][1] = fmaf(a.x, b.y, acc[0][1]);
            acc[0][2] = fmaf(a.x, b.z, acc[0][2]); acc[0][3] = fmaf(a.x, b.w, acc[0][3]);
            acc[1][0] = fmaf(a.y, b.x, acc[1][0]); acc[1][1] = fmaf(a.y, b.y, acc[1][1]);
            acc[1][2] = fmaf(a.y, b.z, acc[1][2]); acc[1][3] = fmaf(a.y, b.w, acc[1][3]);
            acc[2][0] = fmaf(a.z, b.x, acc[2][0]); acc[2][1] = fmaf(a.z, b.y, acc[2][1]);
            acc[2][2] = fmaf(a.z, b.z, acc[2][2]); acc[2][3] = fmaf(a.z, b.w, acc[2][3]);
            acc[3][0] = fmaf(a.w, b.x, acc[3][0]); acc[3][1] = fmaf(a.w, b.y, acc[3][1]);
            acc[3][2] = fmaf(a.w, b.z, acc[3][2]); acc[3][3] = fmaf(a.w, b.w, acc[3][3]);
        }
        __syncthreads();
    }

    #pragma unroll
    for (int i = 0; i < 4; i++) {
        float4 o;
        o.x = acc[i][0] + bias[col0 + tx4 + 0];
        o.y = acc[i][1] + bias[col0 + tx4 + 1];
        o.z = acc[i][2] + bias[col0 + tx4 + 2];
        o.w = acc[i][3] + bias[col0 + tx4 + 3];
        *(float4*)&g_gx[dir][mt][ty4 + i][col0 + tx4] = o;
    }
}

// =================================================================================
// Kernel 2: bidirectional LSTM recurrence.
// Cluster of 8 CTAs = one (direction, batch-group-of-8). Each CTA owns 32 hidden
// units: its 128 W_hh rows (4 gates x 32) live in SMEM as fp32 [k][r] (128 KB).
// h (double-buffered [2][256][8]) is exchanged via DSMEM each step + cluster.sync.
// Grid = 2 dirs * 8 groups * 8 ranks = 128 CTAs, 256 threads.
// =================================================================================
#define REC_SMEM_FLOATS (256 * 128 + 2 * 256 * 8 + 128 * 9)
#define REC_SMEM_BYTES  (REC_SMEM_FLOATS * 4)

__global__ __launch_bounds__(256) __cluster_dims__(8, 1, 1) void lstm_rec_kernel(
    const float* __restrict__ w_hh_f, const float* __restrict__ w_hh_b)
{
    extern __shared__ float smem[];
    float* sW = smem;                        // [256][128]  (k-major, conflict-free reads)
    float* sH = smem + 256 * 128;            // [2][256][8] (buf, k, batch)
    float* sZ = sH + 2 * 256 * 8;            // [128][9]    (padded to kill conflicts)

    cg::cluster_group cluster = cg::this_cluster();
    const unsigned rank = cluster.block_rank();      // 0..7 -> hidden-unit slice
    const int bx  = blockIdx.x;
    const int cid = bx >> 3;                         // 0..15
    const int d   = cid >> 3;                        // direction
    const int b0  = (cid & 7) * 8;                   // batch group base
    const int tid = threadIdx.x;

    const float* __restrict__ Wg = d ? w_hh_b : w_hh_f;

    // Load our 128 W rows into SMEM (transposed to [k][r]).
    for (int i = tid; i < 128 * 256; i += 256) {
        int r = i >> 8, k = i & 255;
        int gate = r >> 5, u = r & 31;
        int j = gate * 256 + rank * 32 + u;
        sW[k * 128 + r] = Wg[(size_t)j * 256 + k];
    }
    // Zero h buffer 0.
    for (int i = tid; i < 256 * 8; i += 256) sH[i] = 0.0f;
    __syncthreads();
    cluster.sync();

    // GEMM-phase mapping: 256 threads = 128 rows x 2 batch-halves.
    const int r    = tid & 127;
    const int bh   = tid >> 7;                 // 0 or 1 -> batches bh*4 .. bh*4+3
    const int gate = r >> 5, u = r & 31;
    const int j    = gate * 256 + rank * 32 + u;
    // Gate-phase mapping: (batch gb, unit gu).
    const int gb = tid >> 5, gu = tid & 31;
    const int hj = rank * 32 + gu;             // owned hidden index

    float c = 0.0f;
    int p = 0;

    for (int s = 0; s < TT; s++) {
        const int t = d ? (TT - 1 - s) : s;

        const float* __restrict__ gxp = &g_gx[d][t][b0 + bh * 4][j];
        float gx0 = gxp[0], gx1 = gxp[1024], gx2 = gxp[2048], gx3 = gxp[3072];

        float a0 = 0.f, a1 = 0.f, a2 = 0.f, a3 = 0.f;
        const float* hb = sH + p * 2048 + bh * 4;
        #pragma unroll 8
        for (int k = 0; k < 256; k++) {
            float  w  = sW[k * 128 + r];
            float4 h4 = *(const float4*)(hb + k * 8);
            a0 = fmaf(w, h4.x, a0); a1 = fmaf(w, h4.y, a1);
            a2 = fmaf(w, h4.z, a2); a3 = fmaf(w, h4.w, a3);
        }
        sZ[r * 9 + bh * 4 + 0] = a0 + gx0;
        sZ[r * 9 + bh * 4 + 1] = a1 + gx1;
        sZ[r * 9 + bh * 4 + 2] = a2 + gx2;
        sZ[r * 9 + bh * 4 + 3] = a3 + gx3;
        __syncthreads();

        // Gates: z order along 4H is [i | f | g | o].
        float zi = sZ[(gu)      * 9 + gb];
        float zf = sZ[(32 + gu) * 9 + gb];
        float zg = sZ[(64 + gu) * 9 + gb];
        float zo = sZ[(96 + gu) * 9 + gb];
        float si = 1.0f / (1.0f + __expf(-zi));
        float sf = 1.0f / (1.0f + __expf(-zf));
        float so = 1.0f / (1.0f + __expf(-zo));
        c = sf * c + si * tanhf(zg);
        float h = so * tanhf(c);

        g_h[d][t][b0 + gb][hj] = h;

        const int pn  = p ^ 1;
        const int off = pn * 2048 + hj * 8 + gb;
        #pragma unroll
        for (int pr = 0; pr < 8; pr++) {
            float* dst = cluster.map_shared_rank(sH, pr);
            dst[off] = h;
        }
        cluster.sync();
        p = pn;
    }
}

// =================================================================================
// Kernel 3: scores[b,t,k] = concat(h_f, h_b)[b,t] . w_fc[k] + b_fc[k]
// 64 blocks (one per batch), 8 warps stride over t, lane = k. w_fc transposed in SMEM.
// =================================================================================
__global__ __launch_bounds__(256) void scores_kernel(
    const float* __restrict__ w_fc, const float* __restrict__ b_fc)
{
    extern __shared__ float sWT[];            // [512][32] = w_fc^T
    const int b   = blockIdx.x;
    const int tid = threadIdx.x;
    for (int i = tid; i < 512 * 32; i += 256) {
        int dd = i & 511, k = i >> 9;
        sWT[dd * 32 + k] = w_fc[k * 512 + dd];
    }
    __syncthreads();

    const int wi = tid >> 5, k = tid & 31;
    const float bias = b_fc[k];
    for (int t = wi; t < TT; t += 8) {
        const float* __restrict__ hf = &g_h[0][t][b][0];
        const float* __restrict__ hb = &g_h[1][t][b][0];
        float acc = bias;
        #pragma unroll 4
        for (int dd = 0; dd < 256; dd++) {
            acc = fmaf(hf[dd], sWT[dd * 32 + k], acc);
            acc = fmaf(hb[dd], sWT[(256 + dd) * 32 + k], acc);
        }
        g_scores[b][t][k] = acc;
    }
}

// =================================================================================
// Kernel 4: CRF — gold-path score + forward algorithm (stable logsumexp).
// One warp per batch element; lane j = CRF state. mask is a contiguous prefix,
// so alpha-freeze under mask == stopping at len.
// =================================================================================
__global__ __launch_bounds__(32) void crf_kernel(
    const int* __restrict__ tags, const int* __restrict__ mask,
    const float* __restrict__ trans)
{
    __shared__ float sT[32 * 32];
    __shared__ float sA[32];
    const int b = blockIdx.x;
    const int j = threadIdx.x;

    for (int i = j; i < 1024; i += 32) sT[i] = trans[i];
    __syncwarp();

    // sequence length
    int len = 0;
    for (int t = j; t < TT; t += 32) len += mask[b * TT + t];
    #pragma unroll
    for (int o = 16; o; o >>= 1) len += __shfl_xor_sync(0xffffffffu, len, o);

    // gold path score
    const int* __restrict__ tg = tags + b * TT;
    float body = 0.0f;
    for (int t = 1 + j; t < len; t += 32) {
        int tp = tg[t - 1], tc = tg[t];
        body += sT[tp * 32 + tc] + g_scores[b][t][tc];
    }
    #pragma unroll
    for (int o = 16; o; o >>= 1) body += __shfl_xor_sync(0xffffffffu, body, o);
    const int t0 = tg[0];
    const float truep = sT[30 * 32 + t0] + g_scores[b][0][t0] + body
                      + sT[tg[len - 1] * 32 + 31];

    // forward algorithm
    float alpha = sT[30 * 32 + j] + g_scores[b][0][j];
    sA[j] = alpha;
    __syncwarp();
    for (int t = 1; t < len; t++) {
        float m = -1e30f;
        #pragma unroll
        for (int i = 0; i < 32; i++) m = fmaxf(m, sA[i] + sT[i * 32 + j]);
        float s = 0.0f;
        #pragma unroll
        for (int i = 0; i < 32; i++) s += __expf(sA[i] + sT[i * 32 + j] - m);
        alpha = g_scores[b][t][j] + m + __logf(s);
        __syncwarp();
        sA[j] = alpha;
        __syncwarp();
    }

    float v = alpha + sT[j * 32 + 31];
    float m = v;
    #pragma unroll
    for (int o = 16; o; o >>= 1) m = fmaxf(m, __shfl_xor_sync(0xffffffffu, m, o));
    float e = __expf(v - m);
    #pragma unroll
    for (int o = 16; o; o >>= 1) e += __shfl_xor_sync(0xffffffffu, e, o);
    if (j == 0) g_loss[b] = (m + __logf(e)) - truep;   // total - true
}

// loss = -sum(true - total) = sum(total - true); fixed-order sum for determinism.
__global__ void finalize_kernel(float* __restrict__ out)
{
    if (threadIdx.x == 0) {
        float s = 0.0f;
        for (int b = 0; b < BB; b++) s += g_loss[b];
        out[0] = s;
    }
}

// =================================================================================
extern "C" void kernel_launch(void* const* d_in, const int* in_sizes, int n_in,
                              void* d_out, int out_size)
{
    const int*   x      = (const int*)  d_in[0];
    const int*   tags   = (const int*)  d_in[1];
    const int*   mask   = (const int*)  d_in[2];
    const float* emb    = (const float*)d_in[3];
    const float* w_ih_f = (const float*)d_in[4];
    const float* w_hh_f = (const float*)d_in[5];
    const float* b_f    = (const float*)d_in[6];
    const float* w_ih_b = (const float*)d_in[7];
    const float* w_hh_b = (const float*)d_in[8];
    const float* b_b    = (const float*)d_in[9];
    const float* w_fc   = (const float*)d_in[10];
    const float* b_fc   = (const float*)d_in[11];
    const float* trans  = (const float*)d_in[12];
    float* out = (float*)d_out;

    cudaFuncSetAttribute(lstm_rec_kernel,
                         cudaFuncAttributeMaxDynamicSharedMemorySize, REC_SMEM_BYTES);
    cudaFuncSetAttribute(scores_kernel,
                         cudaFuncAttributeMaxDynamicSharedMemorySize, 512 * 32 * 4);

    proj_kernel<<<dim3(512, 32), 256>>>(x, emb, w_ih_f, b_f, w_ih_b, b_b);
    lstm_rec_kernel<<<128, 256, REC_SMEM_BYTES>>>(w_hh_f, w_hh_b);
    scores_kernel<<<64, 256, 512 * 32 * 4>>>(w_fc, b_fc);
    crf_kernel<<<64, 32>>>(tags, mask, trans);
    finalize_kernel<<<1, 32>>>(out);
}

// round 5
// speedup vs baseline: 1.3285x; 1.3272x over previous
#include <cuda_runtime.h>
#include <cooperative_groups.h>
#include <math.h>

namespace cg = cooperative_groups;

#define TT 512
#define BB 64
#define NK 32

typedef unsigned long long u64;
union F2U { float2 f; u64 u; };

__device__ __forceinline__ u64 dup2(float w) {
    unsigned int iw = __float_as_uint(w);
    u64 r;
    asm("mov.b64 %0, {%1, %1};" : "=l"(r) : "r"(iw));
    return r;
}
__device__ __forceinline__ void ffma2(u64& d, u64 a, u64 b) {
    asm("fma.rn.f32x2 %0, %1, %2, %0;" : "+l"(d) : "l"(a), "l"(b));
}

// ---------------- scratch (device globals; no allocations allowed) ----------------
__device__ float g_gx[2][TT][BB][1024];     // input projections, both directions
__device__ float g_h[2][TT][BB][256];       // hidden states fwd/bwd
__device__ float g_scores[BB][TT][NK];      // emission scores
__device__ float g_loss[BB];                // per-batch (total - true)

// =================================================================================
// Kernel 1: embedding gather + input projection GEMM (both dirs), FFMA2 inner loop.
// BM=64 (batch rows of one t), BN=64, BK=16; 256 thr; micro-tile 4 rows x 4 cols,
// rows packed as f32x2 pairs, cols duplicated via mov.b64.
// =================================================================================
__global__ __launch_bounds__(256) void proj_kernel(
    const int* __restrict__ x, const float* __restrict__ emb,
    const float* __restrict__ w_f, const float* __restrict__ bf_,
    const float* __restrict__ w_b, const float* __restrict__ bb_)
{
    __shared__ __align__(16) float As[16 * 64];
    __shared__ __align__(16) float Bs[16 * 64];
    __shared__ int sidx[64];

    const int mt   = blockIdx.x;        // time index t
    const int n0   = blockIdx.y * 64;   // output column tile (0..2047)
    const int dir  = n0 >> 10;
    const int col0 = n0 & 1023;
    const float* __restrict__ W    = dir ? w_b : w_f;
    const float* __restrict__ bias = dir ? bb_ : bf_;

    const int tid = threadIdx.x;
    if (tid < 64) sidx[tid] = x[tid * TT + mt];
    __syncthreads();

    const int lm  = tid >> 2;          // 0..63
    const int kq  = (tid & 3) << 2;
    const int ty4 = (tid >> 4) << 2;   // row base
    const int tx4 = (tid & 15) << 2;   // col base

    u64 acc[2][4] = {};                // [rowpair][col]

    for (int k0 = 0; k0 < 256; k0 += 16) {
        float4 av = *(const float4*)&emb[(size_t)sidx[lm] * 256 + k0 + kq];
        float4 bv = *(const float4*)&W[(size_t)(col0 + lm) * 256 + k0 + kq];
        As[(kq + 0) * 64 + lm] = av.x; As[(kq + 1) * 64 + lm] = av.y;
        As[(kq + 2) * 64 + lm] = av.z; As[(kq + 3) * 64 + lm] = av.w;
        Bs[(kq + 0) * 64 + lm] = bv.x; Bs[(kq + 1) * 64 + lm] = bv.y;
        Bs[(kq + 2) * 64 + lm] = bv.z; Bs[(kq + 3) * 64 + lm] = bv.w;
        __syncthreads();

        #pragma unroll
        for (int kk = 0; kk < 16; kk++) {
            ulonglong2 ap = *(const ulonglong2*)&As[kk * 64 + ty4]; // (r0,r1),(r2,r3)
            float4 b = *(const float4*)&Bs[kk * 64 + tx4];
            u64 b0 = dup2(b.x), b1 = dup2(b.y), b2 = dup2(b.z), b3 = dup2(b.w);
            ffma2(acc[0][0], ap.x, b0); ffma2(acc[0][1], ap.x, b1);
            ffma2(acc[0][2], ap.x, b2); ffma2(acc[0][3], ap.x, b3);
            ffma2(acc[1][0], ap.y, b0); ffma2(acc[1][1], ap.y, b1);
            ffma2(acc[1][2], ap.y, b2); ffma2(acc[1][3], ap.y, b3);
        }
        __syncthreads();
    }

    const float4 bq = *(const float4*)&bias[col0 + tx4];
    #pragma unroll
    for (int rp = 0; rp < 2; rp++) {
        F2U v0, v1, v2, v3;
        v0.u = acc[rp][0]; v1.u = acc[rp][1]; v2.u = acc[rp][2]; v3.u = acc[rp][3];
        float4 o0, o1;
        o0.x = v0.f.x + bq.x; o0.y = v1.f.x + bq.y; o0.z = v2.f.x + bq.z; o0.w = v3.f.x + bq.w;
        o1.x = v0.f.y + bq.x; o1.y = v1.f.y + bq.y; o1.z = v2.f.y + bq.z; o1.w = v3.f.y + bq.w;
        *(float4*)&g_gx[dir][mt][ty4 + rp * 2 + 0][col0 + tx4] = o0;
        *(float4*)&g_gx[dir][mt][ty4 + rp * 2 + 1][col0 + tx4] = o1;
    }
}

// =================================================================================
// Kernel 2: bidirectional LSTM recurrence, FFMA2 + k-split.
// Cluster of 8 CTAs = one (direction, batch-group-of-8). CTA owns 32 hidden units
// (128 W rows in SMEM, k-major). 256 thr = 128 rows x 2 k-halves; partials merged
// via padded sZ. h double-buffered [2][256][8], pushed via DSMEM each step.
// =================================================================================
#define REC_SW (256 * 128)
#define REC_SH (2 * 256 * 8)
#define REC_SZ (2 * 128 * 10)
#define REC_SMEM_BYTES ((REC_SW + REC_SH + REC_SZ) * 4)

__global__ __launch_bounds__(256) __cluster_dims__(8, 1, 1) void lstm_rec_kernel(
    const float* __restrict__ w_hh_f, const float* __restrict__ w_hh_b)
{
    extern __shared__ float smem[];
    float* sW = smem;                        // [256][128]  k-major
    float* sH = smem + REC_SW;               // [2][256][8] (buf, k, batch)
    float* sZ = sH + REC_SH;                 // [2][128][10] (kp, row, batch; stride 10)

    cg::cluster_group cluster = cg::this_cluster();
    const unsigned rank = cluster.block_rank();
    const int cid = blockIdx.x >> 3;
    const int d   = cid >> 3;
    const int b0  = (cid & 7) * 8;
    const int tid = threadIdx.x;

    const float* __restrict__ Wg = d ? w_hh_b : w_hh_f;

    // Load our 128 W rows into SMEM (transposed to [k][r]).
    for (int i = tid; i < 128 * 256; i += 256) {
        int r = i >> 8, k = i & 255;
        int gate = r >> 5, u = r & 31;
        int j = gate * 256 + rank * 32 + u;
        sW[k * 128 + r] = Wg[(size_t)j * 256 + k];
    }
    for (int i = tid; i < 256 * 8; i += 256) sH[i] = 0.0f;   // zero h buffer 0
    __syncthreads();
    cluster.sync();

    // GEMM mapping: 128 rows x 2 k-halves.
    const int r  = tid & 127;
    const int kp = tid >> 7;
    // Gate mapping: (batch gb, unit gu).
    const int gb = tid >> 5, gu = tid & 31;
    const int hj = rank * 32 + gu;

    float c = 0.0f;
    int p = 0;

    for (int s = 0; s < TT; s++) {
        const int t = d ? (TT - 1 - s) : s;

        // gate-phase gx loads issued early (L1 flushed by cluster.sync -> L2 hits)
        const float* __restrict__ gxp = &g_gx[d][t][b0 + gb][hj];
        float gxi = gxp[0], gxf = gxp[256], gxg = gxp[512], gxo = gxp[768];

        u64 a01 = 0, a23 = 0, a45 = 0, a67 = 0;
        const float* hb = sH + p * 2048;
        const int kbase = kp << 7;
        #pragma unroll 8
        for (int kk = 0; kk < 128; kk++) {
            const int k = kbase + kk;
            u64 wd = dup2(sW[k * 128 + r]);
            ulonglong2 h4 = *(const ulonglong2*)(hb + k * 8);       // batches 0-3
            ulonglong2 h5 = *(const ulonglong2*)(hb + k * 8 + 4);   // batches 4-7
            ffma2(a01, wd, h4.x); ffma2(a23, wd, h4.y);
            ffma2(a45, wd, h5.x); ffma2(a67, wd, h5.y);
        }
        {
            u64* zp = (u64*)(sZ + kp * 1280 + r * 10);
            zp[0] = a01; zp[1] = a23; zp[2] = a45; zp[3] = a67;
        }
        __syncthreads();

        // Gates (z order along 4H is [i | f | g | o]).
        float zi = sZ[gu * 10 + gb]        + sZ[1280 + gu * 10 + gb]        + gxi;
        float zf = sZ[(32+gu) * 10 + gb]   + sZ[1280 + (32+gu) * 10 + gb]   + gxf;
        float zg = sZ[(64+gu) * 10 + gb]   + sZ[1280 + (64+gu) * 10 + gb]   + gxg;
        float zo = sZ[(96+gu) * 10 + gb]   + sZ[1280 + (96+gu) * 10 + gb]   + gxo;
        float si = 1.0f / (1.0f + __expf(-zi));
        float sf = 1.0f / (1.0f + __expf(-zf));
        float so = 1.0f / (1.0f + __expf(-zo));
        c = sf * c + si * tanhf(zg);
        float h = so * tanhf(c);

        g_h[d][t][b0 + gb][hj] = h;

        const int pn  = p ^ 1;
        const int off = pn * 2048 + hj * 8 + gb;
        #pragma unroll
        for (int pr = 0; pr < 8; pr++) {
            float* dst = cluster.map_shared_rank(sH, pr);
            dst[off] = h;
        }
        cluster.sync();
        p = pn;
    }
}

// =================================================================================
// Kernel 3: scores = concat(h_f,h_b) @ w_fc^T + b_fc as a tiled FFMA2 GEMM.
// Block = (batch b, 64-t tile): M=64, N=32, K=512. 256 thr, micro 4 rows x 2 cols.
// =================================================================================
__global__ __launch_bounds__(256) void scores_kernel(
    const float* __restrict__ w_fc, const float* __restrict__ b_fc)
{
    __shared__ __align__(16) float As[16 * 64];
    __shared__ __align__(16) float Bs[16 * 32];

    const int b   = blockIdx.x;
    const int t0  = blockIdx.y * 64;
    const int tid = threadIdx.x;
    const int lm  = tid >> 2, kq = (tid & 3) << 2;
    const int ty  = tid >> 4, tx = tid & 15;   // rows ty*4.., cols tx*2..

    u64 acc[2][2] = {};

    for (int k0 = 0; k0 < 512; k0 += 16) {
        const int dir = k0 >> 8, dk = k0 & 255;
        float4 av = *(const float4*)&g_h[dir][t0 + lm][b][dk + kq];
        As[(kq + 0) * 64 + lm] = av.x; As[(kq + 1) * 64 + lm] = av.y;
        As[(kq + 2) * 64 + lm] = av.z; As[(kq + 3) * 64 + lm] = av.w;
        for (int q = tid; q < 512; q += 256) {
            int kk = q >> 5, n = q & 31;
            Bs[kk * 32 + n] = w_fc[n * 512 + k0 + kk];
        }
        __syncthreads();

        #pragma unroll
        for (int kk = 0; kk < 16; kk++) {
            ulonglong2 ap = *(const ulonglong2*)&As[kk * 64 + ty * 4];
            float2 bv = *(const float2*)&Bs[kk * 32 + tx * 2];
            u64 b0 = dup2(bv.x), b1 = dup2(bv.y);
            ffma2(acc[0][0], ap.x, b0); ffma2(acc[0][1], ap.x, b1);
            ffma2(acc[1][0], ap.y, b0); ffma2(acc[1][1], ap.y, b1);
        }
        __syncthreads();
    }

    #pragma unroll
    for (int cc = 0; cc < 2; cc++) {
        const int col = tx * 2 + cc;
        const float bias = b_fc[col];
        #pragma unroll
        for (int rp = 0; rp < 2; rp++) {
            F2U v; v.u = acc[rp][cc];
            g_scores[b][t0 + ty * 4 + rp * 2 + 0][col] = v.f.x + bias;
            g_scores[b][t0 + ty * 4 + rp * 2 + 1][col] = v.f.y + bias;
        }
    }
}

// =================================================================================
// Kernel 4: CRF. Transition entries are {0, -10000} -> exp(T) in {1, 0} exactly.
// Forward step: single reference-lane shift (lane 1 = a real tag; spread among
// live states is bounded by per-step score spread, dead states underflow to 0):
//   alpha_j = sc_j + aref + log( sum_i exp(alpha_i - aref) * expT_ij )
// One warp per batch element.
// =================================================================================
__global__ __launch_bounds__(32) void crf_kernel(
    const int* __restrict__ tags, const int* __restrict__ mask,
    const float* __restrict__ trans)
{
    __shared__ float sT[1024];
    __shared__ float sE[1024];
    __shared__ float sA[32];
    const int b = blockIdx.x;
    const int j = threadIdx.x;

    for (int i = j; i < 1024; i += 32) {
        float tv = trans[i];
        sT[i] = tv;
        sE[i] = __expf(tv);        // exactly 1.0 or 0.0
    }
    __syncwarp();

    // sequence length (mask is a contiguous prefix)
    int len = 0;
    for (int t = j; t < TT; t += 32) len += mask[b * TT + t];
    #pragma unroll
    for (int o = 16; o; o >>= 1) len += __shfl_xor_sync(0xffffffffu, len, o);

    // gold path score
    const int* __restrict__ tg = tags + b * TT;
    float body = 0.0f;
    for (int t = 1 + j; t < len; t += 32) {
        int tp = tg[t - 1], tc = tg[t];
        body += sT[tp * 32 + tc] + g_scores[b][t][tc];
    }
    #pragma unroll
    for (int o = 16; o; o >>= 1) body += __shfl_xor_sync(0xffffffffu, body, o);
    const int t0 = tg[0];
    const float truep = sT[30 * 32 + t0] + g_scores[b][0][t0] + body
                      + sT[tg[len - 1] * 32 + 31];

    // forward algorithm
    float alpha = sT[30 * 32 + j] + g_scores[b][0][j];
    for (int t = 1; t < len; t++) {
        float aref = __shfl_sync(0xffffffffu, alpha, 1);
        float e = __expf(alpha - aref);
        sA[j] = e;
        __syncwarp();
        float s0 = 0.f, s1 = 0.f, s2 = 0.f, s3 = 0.f;
        #pragma unroll
        for (int i = 0; i < 32; i += 4) {
            s0 = fmaf(sA[i + 0], sE[(i + 0) * 32 + j], s0);
            s1 = fmaf(sA[i + 1], sE[(i + 1) * 32 + j], s1);
            s2 = fmaf(sA[i + 2], sE[(i + 2) * 32 + j], s2);
            s3 = fmaf(sA[i + 3], sE[(i + 3) * 32 + j], s3);
        }
        float s = (s0 + s1) + (s2 + s3);
        alpha = g_scores[b][t][j] + aref + __logf(s);
        __syncwarp();
    }

    float v = alpha + sT[j * 32 + 31];
    float m = v;
    #pragma unroll
    for (int o = 16; o; o >>= 1) m = fmaxf(m, __shfl_xor_sync(0xffffffffu, m, o));
    float e = __expf(v - m);
    #pragma unroll
    for (int o = 16; o; o >>= 1) e += __shfl_xor_sync(0xffffffffu, e, o);
    if (j == 0) g_loss[b] = (m + __logf(e)) - truep;   // total - true
}

__global__ void finalize_kernel(float* __restrict__ out)
{
    if (threadIdx.x == 0) {
        float s = 0.0f;
        for (int b = 0; b < BB; b++) s += g_loss[b];
        out[0] = s;
    }
}

// =================================================================================
extern "C" void kernel_launch(void* const* d_in, const int* in_sizes, int n_in,
                              void* d_out, int out_size)
{
    const int*   x      = (const int*)  d_in[0];
    const int*   tags   = (const int*)  d_in[1];
    const int*   mask   = (const int*)  d_in[2];
    const float* emb    = (const float*)d_in[3];
    const float* w_ih_f = (const float*)d_in[4];
    const float* w_hh_f = (const float*)d_in[5];
    const float* b_f    = (const float*)d_in[6];
    const float* w_ih_b = (const float*)d_in[7];
    const float* w_hh_b = (const float*)d_in[8];
    const float* b_b    = (const float*)d_in[9];
    const float* w_fc   = (const float*)d_in[10];
    const float* b_fc   = (const float*)d_in[11];
    const float* trans  = (const float*)d_in[12];
    float* out = (float*)d_out;

    cudaFuncSetAttribute(lstm_rec_kernel,
                         cudaFuncAttributeMaxDynamicSharedMemorySize, REC_SMEM_BYTES);

    proj_kernel<<<dim3(512, 32), 256>>>(x, emb, w_ih_f, b_f, w_ih_b, b_b);
    lstm_rec_kernel<<<128, 256, REC_SMEM_BYTES>>>(w_hh_f, w_hh_b);
    scores_kernel<<<dim3(64, 8), 256>>>(w_fc, b_fc);
    crf_kernel<<<64, 32>>>(tags, mask, trans);
    finalize_kernel<<<1, 32>>>(out);
}

// round 7
// speedup vs baseline: 2.5639x; 1.9299x over previous
#include <cuda_runtime.h>
#include <cuda_bf16.h>
#include <cooperative_groups.h>
#include <math.h>

namespace cg = cooperative_groups;

#define TT 512
#define BB 64
#define NK 32

typedef unsigned long long u64;
typedef unsigned int u32;
typedef unsigned short u16;
union F2U { float2 f; u64 u; };

__device__ __forceinline__ u64 dup2(float w) {
    unsigned int iw = __float_as_uint(w);
    u64 r;
    asm("mov.b64 %0, {%1, %1};" : "=l"(r) : "r"(iw));
    return r;
}
__device__ __forceinline__ void ffma2(u64& d, u64 a, u64 b) {
    asm("fma.rn.f32x2 %0, %1, %2, %0;" : "+l"(d) : "l"(a), "l"(b));
}

// ---------------- scratch (device globals; no allocations allowed) ----------------
__device__ float g_gx[2][TT][BB][1024];     // input projections, both directions
__device__ float g_h[2][TT][BB][256];       // hidden states fwd/bwd
__device__ float g_scores[BB][TT][NK];      // emission scores
__device__ float g_loss[BB];                // per-batch (total - true)

// =================================================================================
// Kernel 1: embedding gather + input projection GEMM (R4, FFMA2) — unchanged.
// =================================================================================
__global__ __launch_bounds__(256) void proj_kernel(
    const int* __restrict__ x, const float* __restrict__ emb,
    const float* __restrict__ w_f, const float* __restrict__ bf_,
    const float* __restrict__ w_b, const float* __restrict__ bb_)
{
    __shared__ __align__(16) float As[16 * 64];
    __shared__ __align__(16) float Bs[16 * 64];
    __shared__ int sidx[64];

    const int mt   = blockIdx.x;
    const int n0   = blockIdx.y * 64;
    const int dir  = n0 >> 10;
    const int col0 = n0 & 1023;
    const float* __restrict__ W    = dir ? w_b : w_f;
    const float* __restrict__ bias = dir ? bb_ : bf_;

    const int tid = threadIdx.x;
    if (tid < 64) sidx[tid] = x[tid * TT + mt];
    __syncthreads();

    const int lm  = tid >> 2;
    const int kq  = (tid & 3) << 2;
    const int ty4 = (tid >> 4) << 2;
    const int tx4 = (tid & 15) << 2;

    u64 acc[2][4] = {};

    for (int k0 = 0; k0 < 256; k0 += 16) {
        float4 av = *(const float4*)&emb[(size_t)sidx[lm] * 256 + k0 + kq];
        float4 bv = *(const float4*)&W[(size_t)(col0 + lm) * 256 + k0 + kq];
        As[(kq + 0) * 64 + lm] = av.x; As[(kq + 1) * 64 + lm] = av.y;
        As[(kq + 2) * 64 + lm] = av.z; As[(kq + 3) * 64 + lm] = av.w;
        Bs[(kq + 0) * 64 + lm] = bv.x; Bs[(kq + 1) * 64 + lm] = bv.y;
        Bs[(kq + 2) * 64 + lm] = bv.z; Bs[(kq + 3) * 64 + lm] = bv.w;
        __syncthreads();

        #pragma unroll
        for (int kk = 0; kk < 16; kk++) {
            ulonglong2 ap = *(const ulonglong2*)&As[kk * 64 + ty4];
            float4 b = *(const float4*)&Bs[kk * 64 + tx4];
            u64 b0 = dup2(b.x), b1 = dup2(b.y), b2 = dup2(b.z), b3 = dup2(b.w);
            ffma2(acc[0][0], ap.x, b0); ffma2(acc[0][1], ap.x, b1);
            ffma2(acc[0][2], ap.x, b2); ffma2(acc[0][3], ap.x, b3);
            ffma2(acc[1][0], ap.y, b0); ffma2(acc[1][1], ap.y, b1);
            ffma2(acc[1][2], ap.y, b2); ffma2(acc[1][3], ap.y, b3);
        }
        __syncthreads();
    }

    const float4 bq = *(const float4*)&bias[col0 + tx4];
    #pragma unroll
    for (int rp = 0; rp < 2; rp++) {
        F2U v0, v1, v2, v3;
        v0.u = acc[rp][0]; v1.u = acc[rp][1]; v2.u = acc[rp][2]; v3.u = acc[rp][3];
        float4 o0, o1;
        o0.x = v0.f.x + bq.x; o0.y = v1.f.x + bq.y; o0.z = v2.f.x + bq.z; o0.w = v3.f.x + bq.w;
        o1.x = v0.f.y + bq.x; o1.y = v1.f.y + bq.y; o1.z = v2.f.y + bq.z; o1.w = v3.f.y + bq.w;
        *(float4*)&g_gx[dir][mt][ty4 + rp * 2 + 0][col0 + tx4] = o0;
        *(float4*)&g_gx[dir][mt][ty4 + rp * 2 + 1][col0 + tx4] = o1;
    }
}

// =================================================================================
// Kernel 2: bidirectional LSTM recurrence on HMMA (mma.sync m16n8k16 bf16).
// Cluster of 8 CTAs = one (direction, batch-group-of-8); CTA owns 128 W_hh rows.
// z = Wh*hh + Wh*hl + Wl*hh (bf16 2-term split, fp32 accum) = fp32-accurate.
// 512 thr = 16 warps = 8 m-tiles x 2 k-halves. W fragments live in REGISTERS
// across all 512 steps (+8 frags/warp in SMEM). h exchanged via DSMEM as bf16
// hi/lo u16. Partial D merged through sZ; gates on tid<256.
// =================================================================================
#define SH_HH 0                      // u16 [2][8][264]  (buf, batch, k padded)
#define SH_HL 8448                   // u16 [2][8][264]
#define SH_Z  16896                  // f32 [2][128][10] (khalf, row, batch padded)
#define SH_AX 27136                  // u32 [8][8][32][4] (mtile, frag, lane, reg)
#define LSTM_SMEM (27136 + 32768)

__device__ __forceinline__ void mma16816(
    float& d0, float& d1, float& d2, float& d3,
    u32 a0, u32 a1, u32 a2, u32 a3, u32 b0, u32 b1)
{
    asm volatile(
        "mma.sync.aligned.m16n8k16.row.col.f32.bf16.bf16.f32 "
        "{%0,%1,%2,%3}, {%4,%5,%6,%7}, {%8,%9}, {%0,%1,%2,%3};"
        : "+f"(d0), "+f"(d1), "+f"(d2), "+f"(d3)
        : "r"(a0), "r"(a1), "r"(a2), "r"(a3), "r"(b0), "r"(b1));
}

__device__ __forceinline__ float bf16_hi(float w) {
    return __bfloat162float(__float2bfloat16_rn(w));
}
__device__ __forceinline__ u32 pack_bf16(float lo, float hi) {
    u32 a = (u32)__bfloat16_as_ushort(__float2bfloat16_rn(lo));
    u32 b = (u32)__bfloat16_as_ushort(__float2bfloat16_rn(hi));
    return a | (b << 16);
}

__global__ __launch_bounds__(512) __cluster_dims__(8, 1, 1) void lstm_rec_kernel(
    const float* __restrict__ w_hh_f, const float* __restrict__ w_hh_b)
{
    extern __shared__ char smem[];
    u16*   sHh = (u16*)(smem + SH_HH);
    u16*   sHl = (u16*)(smem + SH_HL);
    float* sZ  = (float*)(smem + SH_Z);
    uint4* sAx = (uint4*)(smem + SH_AX);

    cg::cluster_group cluster = cg::this_cluster();
    const unsigned rank = cluster.block_rank();      // hidden-unit slice 0..7
    const int cid = blockIdx.x >> 3;
    const int d   = cid >> 3;
    const int b0  = (cid & 7) * 8;
    const int tid = threadIdx.x;
    const int wid = tid >> 5, lane = tid & 31;
    const int g = lane >> 2, tig = lane & 3;

    const float* __restrict__ Wg = d ? w_hh_b : w_hh_f;

    // ---- static A fragments: warp (mtile, khalf) ----
    const int mtile = wid >> 1, khalf = wid & 1;
    const int m0 = mtile * 16;

    // global W row for a local row index r (0..127): rows ordered [gate][unit]
    auto jglob = [&](int r) { return ((r >> 5) << 8) + (int)rank * 32 + (r & 31); };
    // build one A fragment (8 elements) at (m0, kb); mode 0 = hi part, 1 = lo part
    auto buildA = [&](int kb, int mode, u32* a) {
        const int r0 = m0 + g, r1 = m0 + g + 8;
        const int kk = kb + 2 * tig;
        const float* p0 = &Wg[(size_t)jglob(r0) * 256];
        const float* p1 = &Wg[(size_t)jglob(r1) * 256];
        float e00 = p0[kk],     e01 = p0[kk + 1];
        float e10 = p1[kk],     e11 = p1[kk + 1];
        float e02 = p0[kk + 8], e03 = p0[kk + 9];
        float e12 = p1[kk + 8], e13 = p1[kk + 9];
        if (mode) {
            e00 -= bf16_hi(e00); e01 -= bf16_hi(e01);
            e10 -= bf16_hi(e10); e11 -= bf16_hi(e11);
            e02 -= bf16_hi(e02); e03 -= bf16_hi(e03);
            e12 -= bf16_hi(e12); e13 -= bf16_hi(e13);
        }
        a[0] = pack_bf16(e00, e01);
        a[1] = pack_bf16(e10, e11);
        a[2] = pack_bf16(e02, e03);
        a[3] = pack_bf16(e12, e13);
    };

    u32 fA[16][4];
    if (khalf == 0) {
        #pragma unroll
        for (int f = 0; f < 16; f++) buildA(16 * f, 0, fA[f]);        // Wh k0-255
    } else {
        #pragma unroll
        for (int f = 0; f < 16; f++) buildA(16 * f, 1, fA[f]);        // Wl k0-255
        #pragma unroll
        for (int f = 0; f < 8; f++) {                                  // Wh k128-255 -> smem
            u32 a[4];
            buildA(128 + 16 * f, 0, a);
            sAx[(mtile * 8 + f) * 32 + lane] = make_uint4(a[0], a[1], a[2], a[3]);
        }
    }

    // zero h buffer 0 (hh and hl)
    for (int i = tid; i < 8 * 264; i += 512) { sHh[i] = 0; sHl[i] = 0; }
    __syncthreads();
    cluster.sync();

    // gate mapping (tid < 256): (batch gb, unit gu)
    const int gb = (tid & 255) >> 5, gu = tid & 31;
    const int hj = (int)rank * 32 + gu;

    float c = 0.0f;
    int p = 0;

    for (int s = 0; s < TT; s++) {
        const int t = d ? (TT - 1 - s) : s;

        // gate-phase gx loads issued early (hidden under GEMM)
        float gxi = 0.f, gxf = 0.f, gxg = 0.f, gxo = 0.f;
        if (tid < 256) {
            const float* __restrict__ gxp = &g_gx[d][t][b0 + gb][hj];
            gxi = gxp[0]; gxf = gxp[256]; gxg = gxp[512]; gxo = gxp[768];
        }

        // ---- GEMM: D[128 x 8] partial per k-half ----
        const u16* Hh = sHh + p * 2112 + g * 264 + 2 * tig;
        const u16* Hl = sHl + p * 2112 + g * 264 + 2 * tig;
        float d0 = 0.f, d1 = 0.f, d2 = 0.f, d3 = 0.f;

        if (khalf == 0) {
            #pragma unroll
            for (int f = 0; f < 16; f++) {          // Wh * hh, k0-255
                u32 bb0 = *(const u32*)(Hh + 16 * f);
                u32 bb1 = *(const u32*)(Hh + 16 * f + 8);
                mma16816(d0, d1, d2, d3, fA[f][0], fA[f][1], fA[f][2], fA[f][3], bb0, bb1);
            }
            #pragma unroll
            for (int f = 0; f < 8; f++) {           // Wh * hl, k0-127
                u32 bb0 = *(const u32*)(Hl + 16 * f);
                u32 bb1 = *(const u32*)(Hl + 16 * f + 8);
                mma16816(d0, d1, d2, d3, fA[f][0], fA[f][1], fA[f][2], fA[f][3], bb0, bb1);
            }
        } else {
            #pragma unroll
            for (int f = 0; f < 8; f++) {           // Wh * hl, k128-255 (frags from smem)
                uint4 a = sAx[(mtile * 8 + f) * 32 + lane];
                u32 bb0 = *(const u32*)(Hl + 128 + 16 * f);
                u32 bb1 = *(const u32*)(Hl + 128 + 16 * f + 8);
                mma16816(d0, d1, d2, d3, a.x, a.y, a.z, a.w, bb0, bb1);
            }
            #pragma unroll
            for (int f = 0; f < 16; f++) {          // Wl * hh, k0-255
                u32 bb0 = *(const u32*)(Hh + 16 * f);
                u32 bb1 = *(const u32*)(Hh + 16 * f + 8);
                mma16816(d0, d1, d2, d3, fA[f][0], fA[f][1], fA[f][2], fA[f][3], bb0, bb1);
            }
        }

        // store partials: D rows = W-rows, cols = batch
        {
            float2* z0 = (float2*)(sZ + khalf * 1280 + (m0 + g) * 10 + 2 * tig);
            float2* z1 = (float2*)(sZ + khalf * 1280 + (m0 + g + 8) * 10 + 2 * tig);
            *z0 = make_float2(d0, d1);
            *z1 = make_float2(d2, d3);
        }
        __syncthreads();

        // ---- gates (tid < 256) ----
        if (tid < 256) {
            float zi = sZ[gu * 10 + gb]           + sZ[1280 + gu * 10 + gb]           + gxi;
            float zf = sZ[(32 + gu) * 10 + gb]    + sZ[1280 + (32 + gu) * 10 + gb]    + gxf;
            float zg = sZ[(64 + gu) * 10 + gb]    + sZ[1280 + (64 + gu) * 10 + gb]    + gxg;
            float zo = sZ[(96 + gu) * 10 + gb]    + sZ[1280 + (96 + gu) * 10 + gb]    + gxo;
            float si = 1.0f / (1.0f + __expf(-zi));
            float sf = 1.0f / (1.0f + __expf(-zf));
            float so = 1.0f / (1.0f + __expf(-zo));
            c = sf * c + si * tanhf(zg);
            float h = so * tanhf(c);

            g_h[d][t][b0 + gb][hj] = h;

            // split h to bf16 hi/lo and push to all 8 peers
            u16 hh = __bfloat16_as_ushort(__float2bfloat16_rn(h));
            float hhf = __bfloat162float(__ushort_as_bfloat16(hh));
            u16 hl = __bfloat16_as_ushort(__float2bfloat16_rn(h - hhf));
            const int pn = p ^ 1;
            const int off = pn * 2112 + gb * 264 + hj;
            #pragma unroll
            for (int pr = 0; pr < 8; pr++) {
                u16* dh = cluster.map_shared_rank(sHh, pr);
                u16* dl = cluster.map_shared_rank(sHl, pr);
                dh[off] = hh;
                dl[off] = hl;
            }
        }
        cluster.sync();
        p ^= 1;
    }
}

// =================================================================================
// Kernel 3: scores = concat(h_f,h_b) @ w_fc^T + b_fc (FFMA2 GEMM, R4 unchanged).
// =================================================================================
__global__ __launch_bounds__(256) void scores_kernel(
    const float* __restrict__ w_fc, const float* __restrict__ b_fc)
{
    __shared__ __align__(16) float As[16 * 64];
    __shared__ __align__(16) float Bs[16 * 32];

    const int b   = blockIdx.x;
    const int t0  = blockIdx.y * 64;
    const int tid = threadIdx.x;
    const int lm  = tid >> 2, kq = (tid & 3) << 2;
    const int ty  = tid >> 4, tx = tid & 15;

    u64 acc[2][2] = {};

    for (int k0 = 0; k0 < 512; k0 += 16) {
        const int dir = k0 >> 8, dk = k0 & 255;
        float4 av = *(const float4*)&g_h[dir][t0 + lm][b][dk + kq];
        As[(kq + 0) * 64 + lm] = av.x; As[(kq + 1) * 64 + lm] = av.y;
        As[(kq + 2) * 64 + lm] = av.z; As[(kq + 3) * 64 + lm] = av.w;
        for (int q = tid; q < 512; q += 256) {
            int kk = q >> 5, n = q & 31;
            Bs[kk * 32 + n] = w_fc[n * 512 + k0 + kk];
        }
        __syncthreads();

        #pragma unroll
        for (int kk = 0; kk < 16; kk++) {
            ulonglong2 ap = *(const ulonglong2*)&As[kk * 64 + ty * 4];
            float2 bv = *(const float2*)&Bs[kk * 32 + tx * 2];
            u64 b0 = dup2(bv.x), b1 = dup2(bv.y);
            ffma2(acc[0][0], ap.x, b0); ffma2(acc[0][1], ap.x, b1);
            ffma2(acc[1][0], ap.y, b0); ffma2(acc[1][1], ap.y, b1);
        }
        __syncthreads();
    }

    #pragma unroll
    for (int cc = 0; cc < 2; cc++) {
        const int col = tx * 2 + cc;
        const float bias = b_fc[col];
        #pragma unroll
        for (int rp = 0; rp < 2; rp++) {
            F2U v; v.u = acc[rp][cc];
            g_scores[b][t0 + ty * 4 + rp * 2 + 0][col] = v.f.x + bias;
            g_scores[b][t0 + ty * 4 + rp * 2 + 1][col] = v.f.y + bias;
        }
    }
}

// =================================================================================
// Kernel 4: CRF (R4 unchanged).
// =================================================================================
__global__ __launch_bounds__(32) void crf_kernel(
    const int* __restrict__ tags, const int* __restrict__ mask,
    const float* __restrict__ trans)
{
    __shared__ float sT[1024];
    __shared__ float sE[1024];
    __shared__ float sA[32];
    const int b = blockIdx.x;
    const int j = threadIdx.x;

    for (int i = j; i < 1024; i += 32) {
        float tv = trans[i];
        sT[i] = tv;
        sE[i] = __expf(tv);
    }
    __syncwarp();

    int len = 0;
    for (int t = j; t < TT; t += 32) len += mask[b * TT + t];
    #pragma unroll
    for (int o = 16; o; o >>= 1) len += __shfl_xor_sync(0xffffffffu, len, o);

    const int* __restrict__ tg = tags + b * TT;
    float body = 0.0f;
    for (int t = 1 + j; t < len; t += 32) {
        int tp = tg[t - 1], tc = tg[t];
        body += sT[tp * 32 + tc] + g_scores[b][t][tc];
    }
    #pragma unroll
    for (int o = 16; o; o >>= 1) body += __shfl_xor_sync(0xffffffffu, body, o);
    const int t0 = tg[0];
    const float truep = sT[30 * 32 + t0] + g_scores[b][0][t0] + body
                      + sT[tg[len - 1] * 32 + 31];

    float alpha = sT[30 * 32 + j] + g_scores[b][0][j];
    for (int t = 1; t < len; t++) {
        float aref = __shfl_sync(0xffffffffu, alpha, 1);
        float e = __expf(alpha - aref);
        sA[j] = e;
        __syncwarp();
        float s0 = 0.f, s1 = 0.f, s2 = 0.f, s3 = 0.f;
        #pragma unroll
        for (int i = 0; i < 32; i += 4) {
            s0 = fmaf(sA[i + 0], sE[(i + 0) * 32 + j], s0);
            s1 = fmaf(sA[i + 1], sE[(i + 1) * 32 + j], s1);
            s2 = fmaf(sA[i + 2], sE[(i + 2) * 32 + j], s2);
            s3 = fmaf(sA[i + 3], sE[(i + 3) * 32 + j], s3);
        }
        float s = (s0 + s1) + (s2 + s3);
        alpha = g_scores[b][t][j] + aref + __logf(s);
        __syncwarp();
    }

    float v = alpha + sT[j * 32 + 31];
    float m = v;
    #pragma unroll
    for (int o = 16; o; o >>= 1) m = fmaxf(m, __shfl_xor_sync(0xffffffffu, m, o));
    float e = __expf(v - m);
    #pragma unroll
    for (int o = 16; o; o >>= 1) e += __shfl_xor_sync(0xffffffffu, e, o);
    if (j == 0) g_loss[b] = (m + __logf(e)) - truep;
}

__global__ void finalize_kernel(float* __restrict__ out)
{
    if (threadIdx.x == 0) {
        float s = 0.0f;
        for (int b = 0; b < BB; b++) s += g_loss[b];
        out[0] = s;
    }
}

// =================================================================================
extern "C" void kernel_launch(void* const* d_in, const int* in_sizes, int n_in,
                              void* d_out, int out_size)
{
    const int*   x      = (const int*)  d_in[0];
    const int*   tags   = (const int*)  d_in[1];
    const int*   mask   = (const int*)  d_in[2];
    const float* emb    = (const float*)d_in[3];
    const float* w_ih_f = (const float*)d_in[4];
    const float* w_hh_f = (const float*)d_in[5];
    const float* b_f    = (const float*)d_in[6];
    const float* w_ih_b = (const float*)d_in[7];
    const float* w_hh_b = (const float*)d_in[8];
    const float* b_b    = (const float*)d_in[9];
    const float* w_fc   = (const float*)d_in[10];
    const float* b_fc   = (const float*)d_in[11];
    const float* trans  = (const float*)d_in[12];
    float* out = (float*)d_out;

    cudaFuncSetAttribute(lstm_rec_kernel,
                         cudaFuncAttributeMaxDynamicSharedMemorySize, LSTM_SMEM);

    proj_kernel<<<dim3(512, 32), 256>>>(x, emb, w_ih_f, b_f, w_ih_b, b_b);
    lstm_rec_kernel<<<128, 512, LSTM_SMEM>>>(w_hh_f, w_hh_b);
    scores_kernel<<<dim3(64, 8), 256>>>(w_fc, b_fc);
    crf_kernel<<<64, 32>>>(tags, mask, trans);
    finalize_kernel<<<1, 32>>>(out);
}

// round 8
// speedup vs baseline: 3.0265x; 1.1804x over previous
#include <cuda_runtime.h>
#include <cuda_bf16.h>
#include <cooperative_groups.h>
#include <math.h>

namespace cg = cooperative_groups;

#define TT 512
#define BB 64
#define NK 32

typedef unsigned long long u64;
typedef unsigned int u32;
typedef unsigned short u16;
union F2U { float2 f; u64 u; };

__device__ __forceinline__ u64 dup2(float w) {
    unsigned int iw = __float_as_uint(w);
    u64 r;
    asm("mov.b64 %0, {%1, %1};" : "=l"(r) : "r"(iw));
    return r;
}
__device__ __forceinline__ void ffma2(u64& d, u64 a, u64 b) {
    asm("fma.rn.f32x2 %0, %1, %2, %0;" : "+l"(d) : "l"(a), "l"(b));
}

// ---------------- scratch (device globals; no allocations allowed) ----------------
__device__ float g_gx[2][TT][BB][1024];     // input projections, both directions
__device__ float g_h[2][TT][BB][256];       // hidden states fwd/bwd
__device__ float g_scores[BB][TT][NK];      // emission scores
__device__ float g_loss[BB];                // per-batch (total - true)

// bf16 hi/lo splits of emb and w_ih (for HMMA fp32-emulated projection GEMM)
__device__ __nv_bfloat16 g_embh[30000 * 256];
__device__ __nv_bfloat16 g_embl[30000 * 256];
__device__ __nv_bfloat16 g_wh[2][1024 * 256];
__device__ __nv_bfloat16 g_wl[2][1024 * 256];

// ---------------- common HMMA helper ------------------------------------------------
__device__ __forceinline__ void mma16816(
    float& d0, float& d1, float& d2, float& d3,
    u32 a0, u32 a1, u32 a2, u32 a3, u32 b0, u32 b1)
{
    asm volatile(
        "mma.sync.aligned.m16n8k16.row.col.f32.bf16.bf16.f32 "
        "{%0,%1,%2,%3}, {%4,%5,%6,%7}, {%8,%9}, {%0,%1,%2,%3};"
        : "+f"(d0), "+f"(d1), "+f"(d2), "+f"(d3)
        : "r"(a0), "r"(a1), "r"(a2), "r"(a3), "r"(b0), "r"(b1));
}

__device__ __forceinline__ float bf16_hi(float w) {
    return __bfloat162float(__float2bfloat16_rn(w));
}
__device__ __forceinline__ u32 pack_bf16(float lo, float hi) {
    u32 a = (u32)__bfloat16_as_ushort(__float2bfloat16_rn(lo));
    u32 b = (u32)__bfloat16_as_ushort(__float2bfloat16_rn(hi));
    return a | (b << 16);
}

// =================================================================================
// Kernel 0: split fp32 -> bf16 hi + bf16 lo
// =================================================================================
__global__ __launch_bounds__(256) void split_kernel(
    const float* __restrict__ src, __nv_bfloat16* __restrict__ hi,
    __nv_bfloat16* __restrict__ lo, int n)
{
    int i = blockIdx.x * 256 + threadIdx.x;
    if (i < n) {
        float v = src[i];
        __nv_bfloat16 h = __float2bfloat16(v);
        hi[i] = h;
        lo[i] = __float2bfloat16(v - __bfloat162float(h));
    }
}

// =================================================================================
// Kernel 1: projection GEMM on HMMA (bf16 2-term split, fp32 accumulate).
//   Per CTA: D[128 x 128].  M-rows: m = (t-half)*64 + b  (t = 2*tp + (m>>6)).
//   K: 12 chunks = 3 passes (Ah*Bh, Ah*Bl, Al*Bh) x 4 k-chunks of 64.
//   A (hi+lo, all 8 chunks) staged once, frag-packed (1 x LDS.128 per A-frag).
//   B chunks frag-packed, double-buffered, LDG-prefetched in regs.
//   8 warps = 4 m x 2 n; warp tile 32 x 64.
// Grid: (16 n-tiles, 256 t-pairs) — nt fast so same-tp CTAs are concurrent (L2 A reuse).
// =================================================================================
#define PJ_A    0            // uint4[8][8][4][32]  (kcv, mt2, ks, lane)   131072 B
#define PJ_B    131072       // uint2[2][16][4][32] (buf, nf, ks, lane)     32768 B
#define PJ_TOK  163840       // int[128]
#define PJ_BIAS 164352       // float[128]
#define PJ_SMEM 164864

__global__ __launch_bounds__(256) void hmma_proj_kernel(
    const int* __restrict__ x,
    const float* __restrict__ bf_, const float* __restrict__ bb_)
{
    extern __shared__ char smem[];
    uint4* sA   = (uint4*)(smem + PJ_A);
    uint2* sB   = (uint2*)(smem + PJ_B);
    int*   sTok = (int*)(smem + PJ_TOK);
    float* sBias= (float*)(smem + PJ_BIAS);

    const int nt  = blockIdx.x;             // 0..15
    const int tp  = blockIdx.y;             // 0..255
    const int dir = nt >> 3;
    const int col0 = (nt & 7) * 128;
    const float* __restrict__ bias = dir ? bb_ : bf_;

    const int tid = threadIdx.x;
    const int wid = tid >> 5, lane = tid & 31;
    const int wm = wid >> 1, wn = wid & 1;       // warp m-row (0..3), n-col (0..1)

    if (tid < 128) {
        sTok[tid] = x[(tid & 63) * TT + 2 * tp + (tid >> 6)];
        sBias[tid] = bias[col0 + tid];
    }
    __syncthreads();

    // ---- stage all 8 A chunks, frag-packed ----
    // unit: tid = mt2*32 + g*4 + ks
    {
        const int mt2 = tid >> 5, g = (tid >> 2) & 7, ks = tid & 3;
        const int m = mt2 * 16 + g;
        const int t0 = sTok[m], t1 = sTok[m + 8];
        #pragma unroll
        for (int kcv = 0; kcv < 8; kcv++) {
            const __nv_bfloat16* __restrict__ src = (kcv < 4) ? g_embh : g_embl;
            const int k0 = (kcv & 3) * 64 + ks * 16;
            float4 r0 = *(const float4*)&src[(size_t)t0 * 256 + k0];
            float4 r1 = *(const float4*)&src[(size_t)t0 * 256 + k0 + 8];
            float4 r2 = *(const float4*)&src[(size_t)t1 * 256 + k0];
            float4 r3 = *(const float4*)&src[(size_t)t1 * 256 + k0 + 8];
            const u32* q0 = (const u32*)&r0; const u32* q1 = (const u32*)&r1;
            const u32* q2 = (const u32*)&r2; const u32* q3 = (const u32*)&r3;
            uint4* dst = sA + ((kcv * 8 + mt2) * 4 + ks) * 32 + g * 4;
            #pragma unroll
            for (int tg = 0; tg < 4; tg++)
                dst[tg] = make_uint4(q0[tg], q2[tg], q1[tg], q3[tg]);
        }
    }

    // ---- B staging helpers (frag-packed): unit u = u2*256+tid -> (nf, g, ks) ----
    float4 pb[2][2];
    auto ldgB = [&](int i) {
        const int p = i >> 2, kc = i & 3;
        const __nv_bfloat16* __restrict__ W = (p == 1) ? g_wl[dir] : g_wh[dir];
        #pragma unroll
        for (int u2 = 0; u2 < 2; u2++) {
            const int u = u2 * 256 + tid;
            const int nf = u >> 5, g = (u >> 2) & 7, ks = u & 3;
            const __nv_bfloat16* src =
                W + (size_t)(col0 + nf * 8 + g) * 256 + kc * 64 + ks * 16;
            pb[u2][0] = *(const float4*)src;
            pb[u2][1] = *(const float4*)(src + 8);
        }
    };
    auto stsB = [&](int buf) {
        #pragma unroll
        for (int u2 = 0; u2 < 2; u2++) {
            const int u = u2 * 256 + tid;
            const int nf = u >> 5, g = (u >> 2) & 7, ks = u & 3;
            const u32* q0 = (const u32*)&pb[u2][0];
            const u32* q1 = (const u32*)&pb[u2][1];
            uint4* dst = (uint4*)(sB + buf * 2048 + ((nf * 4 + ks) * 32 + g * 4));
            dst[0] = make_uint4(q0[0], q1[0], q0[1], q1[1]);
            dst[1] = make_uint4(q0[2], q1[2], q0[3], q1[3]);
        }
    };

    float4 D0[8] = {}, D1[8] = {};   // [nf8] accumulators for the 2 m16-tiles

    ldgB(0); stsB(0);
    __syncthreads();

    for (int i = 0; i < 12; i++) {
        if (i < 11) ldgB(i + 1);

        const int p = i >> 2, kc = i & 3;
        const int kcv = ((p == 2) ? 4 : 0) + kc;
        const int buf = i & 1;
        #pragma unroll
        for (int ks = 0; ks < 4; ks++) {
            uint4 a0 = sA[((kcv * 8 + wm * 2 + 0) * 4 + ks) * 32 + lane];
            uint4 a1 = sA[((kcv * 8 + wm * 2 + 1) * 4 + ks) * 32 + lane];
            #pragma unroll
            for (int nf8 = 0; nf8 < 8; nf8++) {
                uint2 b = sB[buf * 2048 + ((wn * 8 + nf8) * 4 + ks) * 32 + lane];
                mma16816(D0[nf8].x, D0[nf8].y, D0[nf8].z, D0[nf8].w,
                         a0.x, a0.y, a0.z, a0.w, b.x, b.y);
                mma16816(D1[nf8].x, D1[nf8].y, D1[nf8].z, D1[nf8].w,
                         a1.x, a1.y, a1.z, a1.w, b.x, b.y);
            }
        }

        if (i < 11) stsB((i + 1) & 1);
        __syncthreads();
    }

    // ---- epilogue: add bias, store fp32 ----
    const int tig = lane & 3, g = lane >> 2;
    #pragma unroll
    for (int mt = 0; mt < 2; mt++) {
        const float4* Dm = mt ? D1 : D0;
        const int mt2 = wm * 2 + mt;
        #pragma unroll
        for (int half = 0; half < 2; half++) {
            const int m = mt2 * 16 + g + half * 8;
            const int b = m & 63, t = 2 * tp + (m >> 6);
            float* dst = &g_gx[dir][t][b][col0 + wn * 64 + tig * 2];
            #pragma unroll
            for (int nf8 = 0; nf8 < 8; nf8++) {
                float v0 = half ? Dm[nf8].z : Dm[nf8].x;
                float v1 = half ? Dm[nf8].w : Dm[nf8].y;
                const int nb = wn * 64 + nf8 * 8 + tig * 2;
                float2 o = make_float2(v0 + sBias[nb], v1 + sBias[nb + 1]);
                *(float2*)(dst + nf8 * 8) = o;
            }
        }
    }
}

// =================================================================================
// Kernel 2: bidirectional LSTM recurrence on HMMA (R6, unchanged).
// =================================================================================
#define SH_HH 0                      // u16 [2][8][264]  (buf, batch, k padded)
#define SH_HL 8448                   // u16 [2][8][264]
#define SH_Z  16896                  // f32 [2][128][10] (khalf, row, batch padded)
#define SH_AX 27136                  // u32 [8][8][32][4] (mtile, frag, lane, reg)
#define LSTM_SMEM (27136 + 32768)

__global__ __launch_bounds__(512) __cluster_dims__(8, 1, 1) void lstm_rec_kernel(
    const float* __restrict__ w_hh_f, const float* __restrict__ w_hh_b)
{
    extern __shared__ char smem[];
    u16*   sHh = (u16*)(smem + SH_HH);
    u16*   sHl = (u16*)(smem + SH_HL);
    float* sZ  = (float*)(smem + SH_Z);
    uint4* sAx = (uint4*)(smem + SH_AX);

    cg::cluster_group cluster = cg::this_cluster();
    const unsigned rank = cluster.block_rank();
    const int cid = blockIdx.x >> 3;
    const int d   = cid >> 3;
    const int b0  = (cid & 7) * 8;
    const int tid = threadIdx.x;
    const int wid = tid >> 5, lane = tid & 31;
    const int g = lane >> 2, tig = lane & 3;

    const float* __restrict__ Wg = d ? w_hh_b : w_hh_f;

    const int mtile = wid >> 1, khalf = wid & 1;
    const int m0 = mtile * 16;

    auto jglob = [&](int r) { return ((r >> 5) << 8) + (int)rank * 32 + (r & 31); };
    auto buildA = [&](int kb, int mode, u32* a) {
        const int r0 = m0 + g, r1 = m0 + g + 8;
        const int kk = kb + 2 * tig;
        const float* p0 = &Wg[(size_t)jglob(r0) * 256];
        const float* p1 = &Wg[(size_t)jglob(r1) * 256];
        float e00 = p0[kk],     e01 = p0[kk + 1];
        float e10 = p1[kk],     e11 = p1[kk + 1];
        float e02 = p0[kk + 8], e03 = p0[kk + 9];
        float e12 = p1[kk + 8], e13 = p1[kk + 9];
        if (mode) {
            e00 -= bf16_hi(e00); e01 -= bf16_hi(e01);
            e10 -= bf16_hi(e10); e11 -= bf16_hi(e11);
            e02 -= bf16_hi(e02); e03 -= bf16_hi(e03);
            e12 -= bf16_hi(e12); e13 -= bf16_hi(e13);
        }
        a[0] = pack_bf16(e00, e01);
        a[1] = pack_bf16(e10, e11);
        a[2] = pack_bf16(e02, e03);
        a[3] = pack_bf16(e12, e13);
    };

    u32 fA[16][4];
    if (khalf == 0) {
        #pragma unroll
        for (int f = 0; f < 16; f++) buildA(16 * f, 0, fA[f]);
    } else {
        #pragma unroll
        for (int f = 0; f < 16; f++) buildA(16 * f, 1, fA[f]);
        #pragma unroll
        for (int f = 0; f < 8; f++) {
            u32 a[4];
            buildA(128 + 16 * f, 0, a);
            sAx[(mtile * 8 + f) * 32 + lane] = make_uint4(a[0], a[1], a[2], a[3]);
        }
    }

    for (int i = tid; i < 8 * 264; i += 512) { sHh[i] = 0; sHl[i] = 0; }
    __syncthreads();
    cluster.sync();

    const int gb = (tid & 255) >> 5, gu = tid & 31;
    const int hj = (int)rank * 32 + gu;

    float c = 0.0f;
    int p = 0;

    for (int s = 0; s < TT; s++) {
        const int t = d ? (TT - 1 - s) : s;

        float gxi = 0.f, gxf = 0.f, gxg = 0.f, gxo = 0.f;
        if (tid < 256) {
            const float* __restrict__ gxp = &g_gx[d][t][b0 + gb][hj];
            gxi = gxp[0]; gxf = gxp[256]; gxg = gxp[512]; gxo = gxp[768];
        }

        const u16* Hh = sHh + p * 2112 + g * 264 + 2 * tig;
        const u16* Hl = sHl + p * 2112 + g * 264 + 2 * tig;
        float d0 = 0.f, d1 = 0.f, d2 = 0.f, d3 = 0.f;

        if (khalf == 0) {
            #pragma unroll
            for (int f = 0; f < 16; f++) {
                u32 bb0 = *(const u32*)(Hh + 16 * f);
                u32 bb1 = *(const u32*)(Hh + 16 * f + 8);
                mma16816(d0, d1, d2, d3, fA[f][0], fA[f][1], fA[f][2], fA[f][3], bb0, bb1);
            }
            #pragma unroll
            for (int f = 0; f < 8; f++) {
                u32 bb0 = *(const u32*)(Hl + 16 * f);
                u32 bb1 = *(const u32*)(Hl + 16 * f + 8);
                mma16816(d0, d1, d2, d3, fA[f][0], fA[f][1], fA[f][2], fA[f][3], bb0, bb1);
            }
        } else {
            #pragma unroll
            for (int f = 0; f < 8; f++) {
                uint4 a = sAx[(mtile * 8 + f) * 32 + lane];
                u32 bb0 = *(const u32*)(Hl + 128 + 16 * f);
                u32 bb1 = *(const u32*)(Hl + 128 + 16 * f + 8);
                mma16816(d0, d1, d2, d3, a.x, a.y, a.z, a.w, bb0, bb1);
            }
            #pragma unroll
            for (int f = 0; f < 16; f++) {
                u32 bb0 = *(const u32*)(Hh + 16 * f);
                u32 bb1 = *(const u32*)(Hh + 16 * f + 8);
                mma16816(d0, d1, d2, d3, fA[f][0], fA[f][1], fA[f][2], fA[f][3], bb0, bb1);
            }
        }

        {
            float2* z0 = (float2*)(sZ + khalf * 1280 + (m0 + g) * 10 + 2 * tig);
            float2* z1 = (float2*)(sZ + khalf * 1280 + (m0 + g + 8) * 10 + 2 * tig);
            *z0 = make_float2(d0, d1);
            *z1 = make_float2(d2, d3);
        }
        __syncthreads();

        if (tid < 256) {
            float zi = sZ[gu * 10 + gb]           + sZ[1280 + gu * 10 + gb]           + gxi;
            float zf = sZ[(32 + gu) * 10 + gb]    + sZ[1280 + (32 + gu) * 10 + gb]    + gxf;
            float zg = sZ[(64 + gu) * 10 + gb]    + sZ[1280 + (64 + gu) * 10 + gb]    + gxg;
            float zo = sZ[(96 + gu) * 10 + gb]    + sZ[1280 + (96 + gu) * 10 + gb]    + gxo;
            float si = 1.0f / (1.0f + __expf(-zi));
            float sf = 1.0f / (1.0f + __expf(-zf));
            float so = 1.0f / (1.0f + __expf(-zo));
            c = sf * c + si * tanhf(zg);
            float h = so * tanhf(c);

            g_h[d][t][b0 + gb][hj] = h;

            u16 hh = __bfloat16_as_ushort(__float2bfloat16_rn(h));
            float hhf = __bfloat162float(__ushort_as_bfloat16(hh));
            u16 hl = __bfloat16_as_ushort(__float2bfloat16_rn(h - hhf));
            const int pn = p ^ 1;
            const int off = pn * 2112 + gb * 264 + hj;
            #pragma unroll
            for (int pr = 0; pr < 8; pr++) {
                u16* dh = cluster.map_shared_rank(sHh, pr);
                u16* dl = cluster.map_shared_rank(sHl, pr);
                dh[off] = hh;
                dl[off] = hl;
            }
        }
        cluster.sync();
        p ^= 1;
    }
}

// =================================================================================
// Kernel 3: scores = concat(h_f,h_b) @ w_fc^T + b_fc (FFMA2 GEMM, unchanged).
// =================================================================================
__global__ __launch_bounds__(256) void scores_kernel(
    const float* __restrict__ w_fc, const float* __restrict__ b_fc)
{
    __shared__ __align__(16) float As[16 * 64];
    __shared__ __align__(16) float Bs[16 * 32];

    const int b   = blockIdx.x;
    const int t0  = blockIdx.y * 64;
    const int tid = threadIdx.x;
    const int lm  = tid >> 2, kq = (tid & 3) << 2;
    const int ty  = tid >> 4, tx = tid & 15;

    u64 acc[2][2] = {};

    for (int k0 = 0; k0 < 512; k0 += 16) {
        const int dir = k0 >> 8, dk = k0 & 255;
        float4 av = *(const float4*)&g_h[dir][t0 + lm][b][dk + kq];
        As[(kq + 0) * 64 + lm] = av.x; As[(kq + 1) * 64 + lm] = av.y;
        As[(kq + 2) * 64 + lm] = av.z; As[(kq + 3) * 64 + lm] = av.w;
        for (int q = tid; q < 512; q += 256) {
            int kk = q >> 5, n = q & 31;
            Bs[kk * 32 + n] = w_fc[n * 512 + k0 + kk];
        }
        __syncthreads();

        #pragma unroll
        for (int kk = 0; kk < 16; kk++) {
            ulonglong2 ap = *(const ulonglong2*)&As[kk * 64 + ty * 4];
            float2 bv = *(const float2*)&Bs[kk * 32 + tx * 2];
            u64 b0 = dup2(bv.x), b1 = dup2(bv.y);
            ffma2(acc[0][0], ap.x, b0); ffma2(acc[0][1], ap.x, b1);
            ffma2(acc[1][0], ap.y, b0); ffma2(acc[1][1], ap.y, b1);
        }
        __syncthreads();
    }

    #pragma unroll
    for (int cc = 0; cc < 2; cc++) {
        const int col = tx * 2 + cc;
        const float bias = b_fc[col];
        #pragma unroll
        for (int rp = 0; rp < 2; rp++) {
            F2U v; v.u = acc[rp][cc];
            g_scores[b][t0 + ty * 4 + rp * 2 + 0][col] = v.f.x + bias;
            g_scores[b][t0 + ty * 4 + rp * 2 + 1][col] = v.f.y + bias;
        }
    }
}

// =================================================================================
// Kernel 4: CRF (unchanged).
// =================================================================================
__global__ __launch_bounds__(32) void crf_kernel(
    const int* __restrict__ tags, const int* __restrict__ mask,
    const float* __restrict__ trans)
{
    __shared__ float sT[1024];
    __shared__ float sE[1024];
    __shared__ float sA[32];
    const int b = blockIdx.x;
    const int j = threadIdx.x;

    for (int i = j; i < 1024; i += 32) {
        float tv = trans[i];
        sT[i] = tv;
        sE[i] = __expf(tv);
    }
    __syncwarp();

    int len = 0;
    for (int t = j; t < TT; t += 32) len += mask[b * TT + t];
    #pragma unroll
    for (int o = 16; o; o >>= 1) len += __shfl_xor_sync(0xffffffffu, len, o);

    const int* __restrict__ tg = tags + b * TT;
    float body = 0.0f;
    for (int t = 1 + j; t < len; t += 32) {
        int tp = tg[t - 1], tc = tg[t];
        body += sT[tp * 32 + tc] + g_scores[b][t][tc];
    }
    #pragma unroll
    for (int o = 16; o; o >>= 1) body += __shfl_xor_sync(0xffffffffu, body, o);
    const int t0 = tg[0];
    const float truep = sT[30 * 32 + t0] + g_scores[b][0][t0] + body
                      + sT[tg[len - 1] * 32 + 31];

    float alpha = sT[30 * 32 + j] + g_scores[b][0][j];
    for (int t = 1; t < len; t++) {
        float aref = __shfl_sync(0xffffffffu, alpha, 1);
        float e = __expf(alpha - aref);
        sA[j] = e;
        __syncwarp();
        float s0 = 0.f, s1 = 0.f, s2 = 0.f, s3 = 0.f;
        #pragma unroll
        for (int i = 0; i < 32; i += 4) {
            s0 = fmaf(sA[i + 0], sE[(i + 0) * 32 + j], s0);
            s1 = fmaf(sA[i + 1], sE[(i + 1) * 32 + j], s1);
            s2 = fmaf(sA[i + 2], sE[(i + 2) * 32 + j], s2);
            s3 = fmaf(sA[i + 3], sE[(i + 3) * 32 + j], s3);
        }
        float s = (s0 + s1) + (s2 + s3);
        alpha = g_scores[b][t][j] + aref + __logf(s);
        __syncwarp();
    }

    float v = alpha + sT[j * 32 + 31];
    float m = v;
    #pragma unroll
    for (int o = 16; o; o >>= 1) m = fmaxf(m, __shfl_xor_sync(0xffffffffu, m, o));
    float e = __expf(v - m);
    #pragma unroll
    for (int o = 16; o; o >>= 1) e += __shfl_xor_sync(0xffffffffu, e, o);
    if (j == 0) g_loss[b] = (m + __logf(e)) - truep;
}

__global__ void finalize_kernel(float* __restrict__ out)
{
    if (threadIdx.x == 0) {
        float s = 0.0f;
        for (int b = 0; b < BB; b++) s += g_loss[b];
        out[0] = s;
    }
}

// =================================================================================
extern "C" void kernel_launch(void* const* d_in, const int* in_sizes, int n_in,
                              void* d_out, int out_size)
{
    const int*   x      = (const int*)  d_in[0];
    const int*   tags   = (const int*)  d_in[1];
    const int*   mask   = (const int*)  d_in[2];
    const float* emb    = (const float*)d_in[3];
    const float* w_ih_f = (const float*)d_in[4];
    const float* w_hh_f = (const float*)d_in[5];
    const float* b_f    = (const float*)d_in[6];
    const float* w_ih_b = (const float*)d_in[7];
    const float* w_hh_b = (const float*)d_in[8];
    const float* b_b    = (const float*)d_in[9];
    const float* w_fc   = (const float*)d_in[10];
    const float* b_fc   = (const float*)d_in[11];
    const float* trans  = (const float*)d_in[12];
    float* out = (float*)d_out;

    cudaFuncSetAttribute(lstm_rec_kernel,
                         cudaFuncAttributeMaxDynamicSharedMemorySize, LSTM_SMEM);
    cudaFuncSetAttribute(hmma_proj_kernel,
                         cudaFuncAttributeMaxDynamicSharedMemorySize, PJ_SMEM);

    __nv_bfloat16 *p_eh, *p_el, *p_wh, *p_wl;
    cudaGetSymbolAddress((void**)&p_eh, g_embh);
    cudaGetSymbolAddress((void**)&p_el, g_embl);
    cudaGetSymbolAddress((void**)&p_wh, g_wh);
    cudaGetSymbolAddress((void**)&p_wl, g_wl);

    split_kernel<<<30000, 256>>>(emb, p_eh, p_el, 30000 * 256);
    split_kernel<<<1024, 256>>>(w_ih_f, p_wh, p_wl, 1024 * 256);
    split_kernel<<<1024, 256>>>(w_ih_b, p_wh + 1024 * 256, p_wl + 1024 * 256, 1024 * 256);

    hmma_proj_kernel<<<dim3(16, 256), 256, PJ_SMEM>>>(x, b_f, b_b);
    lstm_rec_kernel<<<128, 512, LSTM_SMEM>>>(w_hh_f, w_hh_b);
    scores_kernel<<<dim3(64, 8), 256>>>(w_fc, b_fc);
    crf_kernel<<<64, 32>>>(tags, mask, trans);
    finalize_kernel<<<1, 32>>>(out);
}

// round 9
// speedup vs baseline: 3.0404x; 1.0046x over previous
#include <cuda_runtime.h>
#include <cuda_bf16.h>
#include <cooperative_groups.h>
#include <math.h>

namespace cg = cooperative_groups;

#define TT 512
#define BB 64
#define NK 32

typedef unsigned long long u64;
typedef unsigned int u32;
typedef unsigned short u16;
union F2U { float2 f; u64 u; };

__device__ __forceinline__ u64 dup2(float w) {
    unsigned int iw = __float_as_uint(w);
    u64 r;
    asm("mov.b64 %0, {%1, %1};" : "=l"(r) : "r"(iw));
    return r;
}
__device__ __forceinline__ void ffma2(u64& d, u64 a, u64 b) {
    asm("fma.rn.f32x2 %0, %1, %2, %0;" : "+l"(d) : "l"(a), "l"(b));
}

// ---------------- scratch (device globals; no allocations allowed) ----------------
__device__ float g_gx[2][TT][BB][1024];     // input projections, both directions
__device__ float g_h[2][TT][BB][256];       // hidden states fwd/bwd
__device__ float g_scores[BB][TT][NK];      // emission scores
__device__ float g_loss[BB];                // per-batch (total - true)

// bf16 hi/lo splits of emb and w_ih (for HMMA fp32-emulated projection GEMM)
__device__ __nv_bfloat16 g_embh[30000 * 256];
__device__ __nv_bfloat16 g_embl[30000 * 256];
__device__ __nv_bfloat16 g_wh[2][1024 * 256];
__device__ __nv_bfloat16 g_wl[2][1024 * 256];

// ---------------- helpers ----------------------------------------------------------
__device__ __forceinline__ void mma16816(
    float& d0, float& d1, float& d2, float& d3,
    u32 a0, u32 a1, u32 a2, u32 a3, u32 b0, u32 b1)
{
    asm volatile(
        "mma.sync.aligned.m16n8k16.row.col.f32.bf16.bf16.f32 "
        "{%0,%1,%2,%3}, {%4,%5,%6,%7}, {%8,%9}, {%0,%1,%2,%3};"
        : "+f"(d0), "+f"(d1), "+f"(d2), "+f"(d3)
        : "r"(a0), "r"(a1), "r"(a2), "r"(a3), "r"(b0), "r"(b1));
}

__device__ __forceinline__ float bf16_hi(float w) {
    return __bfloat162float(__float2bfloat16_rn(w));
}
__device__ __forceinline__ u32 pack_bf16(float lo, float hi) {
    u32 a = (u32)__bfloat16_as_ushort(__float2bfloat16_rn(lo));
    u32 b = (u32)__bfloat16_as_ushort(__float2bfloat16_rn(hi));
    return a | (b << 16);
}
__device__ __forceinline__ unsigned smem_u32(const void* p) {
    unsigned a;
    asm("{ .reg .u64 t; cvta.to.shared.u64 t, %1; cvt.u32.u64 %0, t; }" : "=r"(a) : "l"(p));
    return a;
}
__device__ __forceinline__ u32 mapa_u32(u32 addr, u32 r) {
    u32 a;
    asm("mapa.shared::cluster.u32 %0, %1, %2;" : "=r"(a) : "r"(addr), "r"(r));
    return a;
}
__device__ __forceinline__ void st_cluster_u16(u32 addr, u16 v) {
    asm volatile("st.shared::cluster.u16 [%0], %1;" :: "r"(addr), "h"(v) : "memory");
}
__device__ __forceinline__ void mbar_init(u32 addr, u32 cnt) {
    asm volatile("mbarrier.init.shared.b64 [%0], %1;" :: "r"(addr), "r"(cnt) : "memory");
}
__device__ __forceinline__ void mbar_arrive_cluster(u32 addr) {
    asm volatile("mbarrier.arrive.release.cluster.shared::cluster.b64 _, [%0];"
                 :: "r"(addr) : "memory");
}
__device__ __forceinline__ void mbar_wait_acq(u32 addr, u32 phase) {
    asm volatile(
        "{\n\t.reg .pred P;\n\t"
        "W_%=:\n\t"
        "mbarrier.try_wait.parity.acquire.cluster.shared::cta.b64 P, [%0], %1, 0x989680;\n\t"
        "@P bra D_%=;\n\t"
        "bra W_%=;\n\t"
        "D_%=:\n\t}"
        :: "r"(addr), "r"(phase) : "memory");
}

// =================================================================================
// Kernel 0: split fp32 -> bf16 hi + bf16 lo
// =================================================================================
__global__ __launch_bounds__(256) void split_kernel(
    const float* __restrict__ src, __nv_bfloat16* __restrict__ hi,
    __nv_bfloat16* __restrict__ lo, int n)
{
    int i = blockIdx.x * 256 + threadIdx.x;
    if (i < n) {
        float v = src[i];
        __nv_bfloat16 h = __float2bfloat16(v);
        hi[i] = h;
        lo[i] = __float2bfloat16(v - __bfloat162float(h));
    }
}

// =================================================================================
// Kernel 1: projection GEMM on HMMA (bf16 2-term split) — unchanged from R7.
// =================================================================================
#define PJ_A    0
#define PJ_B    131072
#define PJ_TOK  163840
#define PJ_BIAS 164352
#define PJ_SMEM 164864

__global__ __launch_bounds__(256) void hmma_proj_kernel(
    const int* __restrict__ x,
    const float* __restrict__ bf_, const float* __restrict__ bb_)
{
    extern __shared__ char smem[];
    uint4* sA   = (uint4*)(smem + PJ_A);
    uint2* sB   = (uint2*)(smem + PJ_B);
    int*   sTok = (int*)(smem + PJ_TOK);
    float* sBias= (float*)(smem + PJ_BIAS);

    const int nt  = blockIdx.x;
    const int tp  = blockIdx.y;
    const int dir = nt >> 3;
    const int col0 = (nt & 7) * 128;
    const float* __restrict__ bias = dir ? bb_ : bf_;

    const int tid = threadIdx.x;
    const int wid = tid >> 5, lane = tid & 31;
    const int wm = wid >> 1, wn = wid & 1;

    if (tid < 128) {
        sTok[tid] = x[(tid & 63) * TT + 2 * tp + (tid >> 6)];
        sBias[tid] = bias[col0 + tid];
    }
    __syncthreads();

    {
        const int mt2 = tid >> 5, g = (tid >> 2) & 7, ks = tid & 3;
        const int m = mt2 * 16 + g;
        const int t0 = sTok[m], t1 = sTok[m + 8];
        #pragma unroll
        for (int kcv = 0; kcv < 8; kcv++) {
            const __nv_bfloat16* __restrict__ src = (kcv < 4) ? g_embh : g_embl;
            const int k0 = (kcv & 3) * 64 + ks * 16;
            float4 r0 = *(const float4*)&src[(size_t)t0 * 256 + k0];
            float4 r1 = *(const float4*)&src[(size_t)t0 * 256 + k0 + 8];
            float4 r2 = *(const float4*)&src[(size_t)t1 * 256 + k0];
            float4 r3 = *(const float4*)&src[(size_t)t1 * 256 + k0 + 8];
            const u32* q0 = (const u32*)&r0; const u32* q1 = (const u32*)&r1;
            const u32* q2 = (const u32*)&r2; const u32* q3 = (const u32*)&r3;
            uint4* dst = sA + ((kcv * 8 + mt2) * 4 + ks) * 32 + g * 4;
            #pragma unroll
            for (int tg = 0; tg < 4; tg++)
                dst[tg] = make_uint4(q0[tg], q2[tg], q1[tg], q3[tg]);
        }
    }

    float4 pb[2][2];
    auto ldgB = [&](int i) {
        const int p = i >> 2, kc = i & 3;
        const __nv_bfloat16* __restrict__ W = (p == 1) ? g_wl[dir] : g_wh[dir];
        #pragma unroll
        for (int u2 = 0; u2 < 2; u2++) {
            const int u = u2 * 256 + tid;
            const int nf = u >> 5, g = (u >> 2) & 7, ks = u & 3;
            const __nv_bfloat16* src =
                W + (size_t)(col0 + nf * 8 + g) * 256 + kc * 64 + ks * 16;
            pb[u2][0] = *(const float4*)src;
            pb[u2][1] = *(const float4*)(src + 8);
        }
    };
    auto stsB = [&](int buf) {
        #pragma unroll
        for (int u2 = 0; u2 < 2; u2++) {
            const int u = u2 * 256 + tid;
            const int nf = u >> 5, g = (u >> 2) & 7, ks = u & 3;
            const u32* q0 = (const u32*)&pb[u2][0];
            const u32* q1 = (const u32*)&pb[u2][1];
            uint4* dst = (uint4*)(sB + buf * 2048 + ((nf * 4 + ks) * 32 + g * 4));
            dst[0] = make_uint4(q0[0], q1[0], q0[1], q1[1]);
            dst[1] = make_uint4(q0[2], q1[2], q0[3], q1[3]);
        }
    };

    float4 D0[8] = {}, D1[8] = {};

    ldgB(0); stsB(0);
    __syncthreads();

    for (int i = 0; i < 12; i++) {
        if (i < 11) ldgB(i + 1);

        const int p = i >> 2, kc = i & 3;
        const int kcv = ((p == 2) ? 4 : 0) + kc;
        const int buf = i & 1;
        #pragma unroll
        for (int ks = 0; ks < 4; ks++) {
            uint4 a0 = sA[((kcv * 8 + wm * 2 + 0) * 4 + ks) * 32 + lane];
            uint4 a1 = sA[((kcv * 8 + wm * 2 + 1) * 4 + ks) * 32 + lane];
            #pragma unroll
            for (int nf8 = 0; nf8 < 8; nf8++) {
                uint2 b = sB[buf * 2048 + ((wn * 8 + nf8) * 4 + ks) * 32 + lane];
                mma16816(D0[nf8].x, D0[nf8].y, D0[nf8].z, D0[nf8].w,
                         a0.x, a0.y, a0.z, a0.w, b.x, b.y);
                mma16816(D1[nf8].x, D1[nf8].y, D1[nf8].z, D1[nf8].w,
                         a1.x, a1.y, a1.z, a1.w, b.x, b.y);
            }
        }

        if (i < 11) stsB((i + 1) & 1);
        __syncthreads();
    }

    const int tig = lane & 3, g = lane >> 2;
    #pragma unroll
    for (int mt = 0; mt < 2; mt++) {
        const float4* Dm = mt ? D1 : D0;
        const int mt2 = wm * 2 + mt;
        #pragma unroll
        for (int half = 0; half < 2; half++) {
            const int m = mt2 * 16 + g + half * 8;
            const int b = m & 63, t = 2 * tp + (m >> 6);
            float* dst = &g_gx[dir][t][b][col0 + wn * 64 + tig * 2];
            #pragma unroll
            for (int nf8 = 0; nf8 < 8; nf8++) {
                float v0 = half ? Dm[nf8].z : Dm[nf8].x;
                float v1 = half ? Dm[nf8].w : Dm[nf8].y;
                const int nb = wn * 64 + nf8 * 8 + tig * 2;
                float2 o = make_float2(v0 + sBias[nb], v1 + sBias[nb + 1]);
                *(float2*)(dst + nf8 * 8) = o;
            }
        }
    }
}

// =================================================================================
// Kernel 2: bidirectional LSTM recurrence on HMMA.
// R8 changes: 4-way accumulator chains; mbarrier cluster sync (no cluster.sync in
// the step loop, no per-step L1 flush); hoisted mapa for the DSMEM h-push.
// =================================================================================
#define SH_HH 0                      // u16 [2][8][264]
#define SH_HL 8448                   // u16 [2][8][264]
#define SH_Z  16896                  // f32 [2][128][10]
#define SH_AX 27136                  // uint4 [8][8][32]
#define SH_MB 59904                  // mbarrier (8 B)
#define LSTM_SMEM (59904 + 16)

__global__ __launch_bounds__(512) __cluster_dims__(8, 1, 1) void lstm_rec_kernel(
    const float* __restrict__ w_hh_f, const float* __restrict__ w_hh_b)
{
    extern __shared__ char smem[];
    u16*   sHh = (u16*)(smem + SH_HH);
    u16*   sHl = (u16*)(smem + SH_HL);
    float* sZ  = (float*)(smem + SH_Z);
    uint4* sAx = (uint4*)(smem + SH_AX);
    const u32 mb = smem_u32(smem + SH_MB);

    cg::cluster_group cluster = cg::this_cluster();
    const unsigned rank = cluster.block_rank();
    const int cid = blockIdx.x >> 3;
    const int d   = cid >> 3;
    const int b0  = (cid & 7) * 8;
    const int tid = threadIdx.x;
    const int wid = tid >> 5, lane = tid & 31;
    const int g = lane >> 2, tig = lane & 3;

    const float* __restrict__ Wg = d ? w_hh_b : w_hh_f;

    const int mtile = wid >> 1, khalf = wid & 1;
    const int m0 = mtile * 16;

    auto jglob = [&](int r) { return ((r >> 5) << 8) + (int)rank * 32 + (r & 31); };
    auto buildA = [&](int kb, int mode, u32* a) {
        const int r0 = m0 + g, r1 = m0 + g + 8;
        const int kk = kb + 2 * tig;
        const float* p0 = &Wg[(size_t)jglob(r0) * 256];
        const float* p1 = &Wg[(size_t)jglob(r1) * 256];
        float e00 = p0[kk],     e01 = p0[kk + 1];
        float e10 = p1[kk],     e11 = p1[kk + 1];
        float e02 = p0[kk + 8], e03 = p0[kk + 9];
        float e12 = p1[kk + 8], e13 = p1[kk + 9];
        if (mode) {
            e00 -= bf16_hi(e00); e01 -= bf16_hi(e01);
            e10 -= bf16_hi(e10); e11 -= bf16_hi(e11);
            e02 -= bf16_hi(e02); e03 -= bf16_hi(e03);
            e12 -= bf16_hi(e12); e13 -= bf16_hi(e13);
        }
        a[0] = pack_bf16(e00, e01);
        a[1] = pack_bf16(e10, e11);
        a[2] = pack_bf16(e02, e03);
        a[3] = pack_bf16(e12, e13);
    };

    u32 fA[16][4];
    if (khalf == 0) {
        #pragma unroll
        for (int f = 0; f < 16; f++) buildA(16 * f, 0, fA[f]);
    } else {
        #pragma unroll
        for (int f = 0; f < 16; f++) buildA(16 * f, 1, fA[f]);
        #pragma unroll
        for (int f = 0; f < 8; f++) {
            u32 a[4];
            buildA(128 + 16 * f, 0, a);
            sAx[(mtile * 8 + f) * 32 + lane] = make_uint4(a[0], a[1], a[2], a[3]);
        }
    }

    for (int i = tid; i < 8 * 264; i += 512) { sHh[i] = 0; sHl[i] = 0; }
    if (tid == 0) mbar_init(mb, 8);
    __syncthreads();
    cluster.sync();                      // one-time: zeros + mbarrier init visible

    const int gb = (tid & 255) >> 5, gu = tid & 31;
    const int hj = (int)rank * 32 + gu;

    // hoisted DSMEM bases: peer hh base; hl base = hh base + (SH_HL - SH_HH)
    u32 pbase[8];
    {
        const u32 la = smem_u32(sHh);
        #pragma unroll
        for (int pr = 0; pr < 8; pr++) pbase[pr] = mapa_u32(la, pr);
    }
    const u32 mb_peer = (tid < 8) ? mapa_u32(mb, tid) : 0;

    float c = 0.0f;
    int p = 0;

    for (int s = 0; s < TT; s++) {
        const int t = d ? (TT - 1 - s) : s;

        float gxi = 0.f, gxf = 0.f, gxg = 0.f, gxo = 0.f;
        if (tid < 256) {
            const float* __restrict__ gxp = &g_gx[d][t][b0 + gb][hj];
            gxi = gxp[0]; gxf = gxp[256]; gxg = gxp[512]; gxo = gxp[768];
        }

        // ---- GEMM with 4 independent accumulator chains ----
        const u16* Hh = sHh + p * 2112 + g * 264 + 2 * tig;
        const u16* Hl = sHl + p * 2112 + g * 264 + 2 * tig;
        float ac[4][4] = {};

        if (khalf == 0) {
            #pragma unroll
            for (int f = 0; f < 16; f++) {
                u32 bb0 = *(const u32*)(Hh + 16 * f);
                u32 bb1 = *(const u32*)(Hh + 16 * f + 8);
                mma16816(ac[f & 3][0], ac[f & 3][1], ac[f & 3][2], ac[f & 3][3],
                         fA[f][0], fA[f][1], fA[f][2], fA[f][3], bb0, bb1);
            }
            #pragma unroll
            for (int f = 0; f < 8; f++) {
                u32 bb0 = *(const u32*)(Hl + 16 * f);
                u32 bb1 = *(const u32*)(Hl + 16 * f + 8);
                mma16816(ac[f & 3][0], ac[f & 3][1], ac[f & 3][2], ac[f & 3][3],
                         fA[f][0], fA[f][1], fA[f][2], fA[f][3], bb0, bb1);
            }
        } else {
            #pragma unroll
            for (int f = 0; f < 8; f++) {
                uint4 a = sAx[(mtile * 8 + f) * 32 + lane];
                u32 bb0 = *(const u32*)(Hl + 128 + 16 * f);
                u32 bb1 = *(const u32*)(Hl + 128 + 16 * f + 8);
                mma16816(ac[f & 3][0], ac[f & 3][1], ac[f & 3][2], ac[f & 3][3],
                         a.x, a.y, a.z, a.w, bb0, bb1);
            }
            #pragma unroll
            for (int f = 0; f < 16; f++) {
                u32 bb0 = *(const u32*)(Hh + 16 * f);
                u32 bb1 = *(const u32*)(Hh + 16 * f + 8);
                mma16816(ac[f & 3][0], ac[f & 3][1], ac[f & 3][2], ac[f & 3][3],
                         fA[f][0], fA[f][1], fA[f][2], fA[f][3], bb0, bb1);
            }
        }
        float d0 = (ac[0][0] + ac[1][0]) + (ac[2][0] + ac[3][0]);
        float d1 = (ac[0][1] + ac[1][1]) + (ac[2][1] + ac[3][1]);
        float d2 = (ac[0][2] + ac[1][2]) + (ac[2][2] + ac[3][2]);
        float d3 = (ac[0][3] + ac[1][3]) + (ac[2][3] + ac[3][3]);

        {
            float2* z0 = (float2*)(sZ + khalf * 1280 + (m0 + g) * 10 + 2 * tig);
            float2* z1 = (float2*)(sZ + khalf * 1280 + (m0 + g + 8) * 10 + 2 * tig);
            *z0 = make_float2(d0, d1);
            *z1 = make_float2(d2, d3);
        }
        __syncthreads();

        const int pn = p ^ 1;
        if (tid < 256) {
            float zi = sZ[gu * 10 + gb]           + sZ[1280 + gu * 10 + gb]           + gxi;
            float zf = sZ[(32 + gu) * 10 + gb]    + sZ[1280 + (32 + gu) * 10 + gb]    + gxf;
            float zg = sZ[(64 + gu) * 10 + gb]    + sZ[1280 + (64 + gu) * 10 + gb]    + gxg;
            float zo = sZ[(96 + gu) * 10 + gb]    + sZ[1280 + (96 + gu) * 10 + gb]    + gxo;
            float si = 1.0f / (1.0f + __expf(-zi));
            float sf = 1.0f / (1.0f + __expf(-zf));
            float so = 1.0f / (1.0f + __expf(-zo));
            c = sf * c + si * tanhf(zg);
            float h = so * tanhf(c);

            g_h[d][t][b0 + gb][hj] = h;

            u16 hh = __bfloat16_as_ushort(__float2bfloat16_rn(h));
            float hhf = __bfloat162float(__ushort_as_bfloat16(hh));
            u16 hl = __bfloat16_as_ushort(__float2bfloat16_rn(h - hhf));
            const u32 offb = (u32)(pn * 2112 + gb * 264 + hj) * 2;
            #pragma unroll
            for (int pr = 0; pr < 8; pr++) {
                st_cluster_u16(pbase[pr] + offb, hh);
                st_cluster_u16(pbase[pr] + (SH_HL - SH_HH) + offb, hl);
            }
        }
        __syncthreads();                          // all local stores issued
        if (tid < 8) mbar_arrive_cluster(mb_peer); // release to all peers
        mbar_wait_acq(mb, (u32)(s & 1));           // acquire peers' stores
        p = pn;
    }
    cluster.sync();                                // exit safety
}

// =================================================================================
// Kernel 3: scores = concat(h_f,h_b) @ w_fc^T + b_fc (FFMA2 GEMM, unchanged).
// =================================================================================
__global__ __launch_bounds__(256) void scores_kernel(
    const float* __restrict__ w_fc, const float* __restrict__ b_fc)
{
    __shared__ __align__(16) float As[16 * 64];
    __shared__ __align__(16) float Bs[16 * 32];

    const int b   = blockIdx.x;
    const int t0  = blockIdx.y * 64;
    const int tid = threadIdx.x;
    const int lm  = tid >> 2, kq = (tid & 3) << 2;
    const int ty  = tid >> 4, tx = tid & 15;

    u64 acc[2][2] = {};

    for (int k0 = 0; k0 < 512; k0 += 16) {
        const int dir = k0 >> 8, dk = k0 & 255;
        float4 av = *(const float4*)&g_h[dir][t0 + lm][b][dk + kq];
        As[(kq + 0) * 64 + lm] = av.x; As[(kq + 1) * 64 + lm] = av.y;
        As[(kq + 2) * 64 + lm] = av.z; As[(kq + 3) * 64 + lm] = av.w;
        for (int q = tid; q < 512; q += 256) {
            int kk = q >> 5, n = q & 31;
            Bs[kk * 32 + n] = w_fc[n * 512 + k0 + kk];
        }
        __syncthreads();

        #pragma unroll
        for (int kk = 0; kk < 16; kk++) {
            ulonglong2 ap = *(const ulonglong2*)&As[kk * 64 + ty * 4];
            float2 bv = *(const float2*)&Bs[kk * 32 + tx * 2];
            u64 b0 = dup2(bv.x), b1 = dup2(bv.y);
            ffma2(acc[0][0], ap.x, b0); ffma2(acc[0][1], ap.x, b1);
            ffma2(acc[1][0], ap.y, b0); ffma2(acc[1][1], ap.y, b1);
        }
        __syncthreads();
    }

    #pragma unroll
    for (int cc = 0; cc < 2; cc++) {
        const int col = tx * 2 + cc;
        const float bias = b_fc[col];
        #pragma unroll
        for (int rp = 0; rp < 2; rp++) {
            F2U v; v.u = acc[rp][cc];
            g_scores[b][t0 + ty * 4 + rp * 2 + 0][col] = v.f.x + bias;
            g_scores[b][t0 + ty * 4 + rp * 2 + 1][col] = v.f.y + bias;
        }
    }
}

// =================================================================================
// Kernel 4: CRF. R8: E matrix in registers + float4 broadcast loads of exp(alpha);
// summation order bit-identical to R7.
// =================================================================================
__global__ __launch_bounds__(32) void crf_kernel(
    const int* __restrict__ tags, const int* __restrict__ mask,
    const float* __restrict__ trans)
{
    __shared__ float sT[1024];
    __shared__ float sE[1024];
    __shared__ __align__(16) float sA[32];
    const int b = blockIdx.x;
    const int j = threadIdx.x;

    for (int i = j; i < 1024; i += 32) {
        float tv = trans[i];
        sT[i] = tv;
        sE[i] = __expf(tv);
    }
    __syncwarp();

    float Ereg[32];
    #pragma unroll
    for (int i = 0; i < 32; i++) Ereg[i] = sE[i * 32 + j];

    int len = 0;
    for (int t = j; t < TT; t += 32) len += mask[b * TT + t];
    #pragma unroll
    for (int o = 16; o; o >>= 1) len += __shfl_xor_sync(0xffffffffu, len, o);

    const int* __restrict__ tg = tags + b * TT;
    float body = 0.0f;
    for (int t = 1 + j; t < len; t += 32) {
        int tp = tg[t - 1], tc = tg[t];
        body += sT[tp * 32 + tc] + g_scores[b][t][tc];
    }
    #pragma unroll
    for (int o = 16; o; o >>= 1) body += __shfl_xor_sync(0xffffffffu, body, o);
    const int t0 = tg[0];
    const float truep = sT[30 * 32 + t0] + g_scores[b][0][t0] + body
                      + sT[tg[len - 1] * 32 + 31];

    float alpha = sT[30 * 32 + j] + g_scores[b][0][j];
    for (int t = 1; t < len; t++) {
        float aref = __shfl_sync(0xffffffffu, alpha, 1);
        float e = __expf(alpha - aref);
        sA[j] = e;
        __syncwarp();
        float s0 = 0.f, s1 = 0.f, s2 = 0.f, s3 = 0.f;
        const float4* A4 = (const float4*)sA;
        #pragma unroll
        for (int i = 0; i < 8; i++) {
            float4 ev = A4[i];
            s0 = fmaf(ev.x, Ereg[4 * i + 0], s0);
            s1 = fmaf(ev.y, Ereg[4 * i + 1], s1);
            s2 = fmaf(ev.z, Ereg[4 * i + 2], s2);
            s3 = fmaf(ev.w, Ereg[4 * i + 3], s3);
        }
        float s = (s0 + s1) + (s2 + s3);
        alpha = g_scores[b][t][j] + aref + __logf(s);
        __syncwarp();
    }

    float v = alpha + sT[j * 32 + 31];
    float m = v;
    #pragma unroll
    for (int o = 16; o; o >>= 1) m = fmaxf(m, __shfl_xor_sync(0xffffffffu, m, o));
    float e = __expf(v - m);
    #pragma unroll
    for (int o = 16; o; o >>= 1) e += __shfl_xor_sync(0xffffffffu, e, o);
    if (j == 0) g_loss[b] = (m + __logf(e)) - truep;
}

__global__ void finalize_kernel(float* __restrict__ out)
{
    if (threadIdx.x == 0) {
        float s = 0.0f;
        for (int b = 0; b < BB; b++) s += g_loss[b];
        out[0] = s;
    }
}

// =================================================================================
extern "C" void kernel_launch(void* const* d_in, const int* in_sizes, int n_in,
                              void* d_out, int out_size)
{
    const int*   x      = (const int*)  d_in[0];
    const int*   tags   = (const int*)  d_in[1];
    const int*   mask   = (const int*)  d_in[2];
    const float* emb    = (const float*)d_in[3];
    const float* w_ih_f = (const float*)d_in[4];
    const float* w_hh_f = (const float*)d_in[5];
    const float* b_f    = (const float*)d_in[6];
    const float* w_ih_b = (const float*)d_in[7];
    const float* w_hh_b = (const float*)d_in[8];
    const float* b_b    = (const float*)d_in[9];
    const float* w_fc   = (const float*)d_in[10];
    const float* b_fc   = (const float*)d_in[11];
    const float* trans  = (const float*)d_in[12];
    float* out = (float*)d_out;

    cudaFuncSetAttribute(lstm_rec_kernel,
                         cudaFuncAttributeMaxDynamicSharedMemorySize, LSTM_SMEM);
    cudaFuncSetAttribute(hmma_proj_kernel,
                         cudaFuncAttributeMaxDynamicSharedMemorySize, PJ_SMEM);

    __nv_bfloat16 *p_eh, *p_el, *p_wh, *p_wl;
    cudaGetSymbolAddress((void**)&p_eh, g_embh);
    cudaGetSymbolAddress((void**)&p_el, g_embl);
    cudaGetSymbolAddress((void**)&p_wh, g_wh);
    cudaGetSymbolAddress((void**)&p_wl, g_wl);

    split_kernel<<<30000, 256>>>(emb, p_eh, p_el, 30000 * 256);
    split_kernel<<<1024, 256>>>(w_ih_f, p_wh, p_wl, 1024 * 256);
    split_kernel<<<1024, 256>>>(w_ih_b, p_wh + 1024 * 256, p_wl + 1024 * 256, 1024 * 256);

    hmma_proj_kernel<<<dim3(16, 256), 256, PJ_SMEM>>>(x, b_f, b_b);
    lstm_rec_kernel<<<128, 512, LSTM_SMEM>>>(w_hh_f, w_hh_b);
    scores_kernel<<<dim3(64, 8), 256>>>(w_fc, b_fc);
    crf_kernel<<<64, 32>>>(tags, mask, trans);
    finalize_kernel<<<1, 32>>>(out);
}

// round 10
// speedup vs baseline: 3.2187x; 1.0587x over previous
#include <cuda_runtime.h>
#include <cuda_bf16.h>
#include <cooperative_groups.h>
#include <math.h>

namespace cg = cooperative_groups;

#define TT 512
#define BB 64
#define NK 32

typedef unsigned long long u64;
typedef unsigned int u32;
typedef unsigned short u16;
union F2U { float2 f; u64 u; };

__device__ __forceinline__ u64 dup2(float w) {
    unsigned int iw = __float_as_uint(w);
    u64 r;
    asm("mov.b64 %0, {%1, %1};" : "=l"(r) : "r"(iw));
    return r;
}
__device__ __forceinline__ void ffma2(u64& d, u64 a, u64 b) {
    asm("fma.rn.f32x2 %0, %1, %2, %0;" : "+l"(d) : "l"(a), "l"(b));
}

// ---------------- scratch (device globals; no allocations allowed) ----------------
__device__ float g_gx[2][TT][BB][1024];     // input projections, both directions
__device__ float g_h[2][TT][BB][256];       // hidden states fwd/bwd
__device__ float g_scores[BB][TT][NK];      // emission scores
__device__ float g_loss[BB];                // per-batch (total - true)

// bf16 hi/lo splits of emb and w_ih (for HMMA fp32-emulated projection GEMM)
__device__ __nv_bfloat16 g_embh[30000 * 256];
__device__ __nv_bfloat16 g_embl[30000 * 256];
__device__ __nv_bfloat16 g_wh[2][1024 * 256];
__device__ __nv_bfloat16 g_wl[2][1024 * 256];

// ---------------- helpers ----------------------------------------------------------
__device__ __forceinline__ void mma16816(
    float& d0, float& d1, float& d2, float& d3,
    u32 a0, u32 a1, u32 a2, u32 a3, u32 b0, u32 b1)
{
    asm volatile(
        "mma.sync.aligned.m16n8k16.row.col.f32.bf16.bf16.f32 "
        "{%0,%1,%2,%3}, {%4,%5,%6,%7}, {%8,%9}, {%0,%1,%2,%3};"
        : "+f"(d0), "+f"(d1), "+f"(d2), "+f"(d3)
        : "r"(a0), "r"(a1), "r"(a2), "r"(a3), "r"(b0), "r"(b1));
}
__device__ __forceinline__ void mma4(float4& D, uint4 a, uint2 b) {
    mma16816(D.x, D.y, D.z, D.w, a.x, a.y, a.z, a.w, b.x, b.y);
}

__device__ __forceinline__ float bf16_hi(float w) {
    return __bfloat162float(__float2bfloat16_rn(w));
}
__device__ __forceinline__ u32 pack_bf16(float lo, float hi) {
    u32 a = (u32)__bfloat16_as_ushort(__float2bfloat16_rn(lo));
    u32 b = (u32)__bfloat16_as_ushort(__float2bfloat16_rn(hi));
    return a | (b << 16);
}
__device__ __forceinline__ unsigned smem_u32(const void* p) {
    unsigned a;
    asm("{ .reg .u64 t; cvta.to.shared.u64 t, %1; cvt.u32.u64 %0, t; }" : "=r"(a) : "l"(p));
    return a;
}
__device__ __forceinline__ u32 mapa_u32(u32 addr, u32 r) {
    u32 a;
    asm("mapa.shared::cluster.u32 %0, %1, %2;" : "=r"(a) : "r"(addr), "r"(r));
    return a;
}
__device__ __forceinline__ void st_cluster_u16(u32 addr, u16 v) {
    asm volatile("st.shared::cluster.u16 [%0], %1;" :: "r"(addr), "h"(v) : "memory");
}
__device__ __forceinline__ void mbar_init(u32 addr, u32 cnt) {
    asm volatile("mbarrier.init.shared.b64 [%0], %1;" :: "r"(addr), "r"(cnt) : "memory");
}
__device__ __forceinline__ void mbar_arrive_cluster(u32 addr) {
    asm volatile("mbarrier.arrive.release.cluster.shared::cluster.b64 _, [%0];"
                 :: "r"(addr) : "memory");
}
__device__ __forceinline__ void mbar_wait_acq(u32 addr, u32 phase) {
    asm volatile(
        "{\n\t.reg .pred P;\n\t"
        "W_%=:\n\t"
        "mbarrier.try_wait.parity.acquire.cluster.shared::cta.b64 P, [%0], %1, 0x989680;\n\t"
        "@P bra D_%=;\n\t"
        "bra W_%=;\n\t"
        "D_%=:\n\t}"
        :: "r"(addr), "r"(phase) : "memory");
}

// =================================================================================
// Kernel 0: fused bf16 hi/lo split of emb, w_ih_f, w_ih_b (one launch).
// =================================================================================
__global__ __launch_bounds__(256) void split3_kernel(
    const float* __restrict__ emb,
    const float* __restrict__ wf, const float* __restrict__ wb,
    __nv_bfloat16* __restrict__ eh, __nv_bfloat16* __restrict__ el,
    __nv_bfloat16* __restrict__ wh, __nv_bfloat16* __restrict__ wl)
{
    const int bid = blockIdx.x;
    const float* src;
    __nv_bfloat16 *hi, *lo;
    int i;
    if (bid < 30000) {
        i = bid * 256 + threadIdx.x;
        src = emb; hi = eh; lo = el;
    } else if (bid < 31024) {
        i = (bid - 30000) * 256 + threadIdx.x;
        src = wf; hi = wh; lo = wl;
    } else {
        i = (bid - 31024) * 256 + threadIdx.x;
        src = wb; hi = wh + 1024 * 256; lo = wl + 1024 * 256;
    }
    float v = src[i];
    __nv_bfloat16 h = __float2bfloat16(v);
    hi[i] = h;
    lo[i] = __float2bfloat16(v - __bfloat162float(h));
}

// =================================================================================
// Kernel 1: projection GEMM on HMMA — R9: kc-outer split-term reuse.
//   Per CTA: D[128 x 128].  Per k-chunk (64 k), stage {Ah, Al, Bh, Bl} double-
//   buffered; issue Ah*Bh + Al*Bh from one B-frag load and Ah*Bl from one A-frag
//   load.  LDS bytes -33%, B LDG/STS -50% vs pass-major.
// =================================================================================
#define PJ_A    0            // uint4[2 buf][2 var][8 mt][4 ks][32 lane]  65536 B
#define PJ_B    65536        // uint2[2 buf][2 var][16 nf][4 ks][32 lane] 65536 B
#define PJ_TOK  131072       // int[128]
#define PJ_BIAS 131584       // float[128]
#define PJ_SMEM 132096

__global__ __launch_bounds__(256) void hmma_proj_kernel(
    const int* __restrict__ x,
    const float* __restrict__ bf_, const float* __restrict__ bb_)
{
    extern __shared__ char smem[];
    uint4* sA   = (uint4*)(smem + PJ_A);
    uint2* sB   = (uint2*)(smem + PJ_B);
    int*   sTok = (int*)(smem + PJ_TOK);
    float* sBias= (float*)(smem + PJ_BIAS);

    const int nt  = blockIdx.x;
    const int tp  = blockIdx.y;
    const int dir = nt >> 3;
    const int col0 = (nt & 7) * 128;
    const float* __restrict__ bias = dir ? bb_ : bf_;

    const int tid = threadIdx.x;
    const int wid = tid >> 5, lane = tid & 31;
    const int wm = wid >> 1, wn = wid & 1;

    if (tid < 128) {
        sTok[tid] = x[(tid & 63) * TT + 2 * tp + (tid >> 6)];
        sBias[tid] = bias[col0 + tid];
    }
    __syncthreads();

    // thread staging coords (A): unit = (mt2, g, ks)
    const int amt2 = tid >> 5, ag = (tid >> 2) & 7, aks = tid & 3;
    const int am = amt2 * 16 + ag;
    const int at0 = sTok[am], at1 = sTok[am + 8];

    float4 pa[2][4];     // [var][rowquad]
    float4 pbv[2][2][2]; // [var][rep][half]

    auto ldgAB = [&](int kc) {
        const int k0 = kc * 64 + aks * 16;
        #pragma unroll
        for (int v = 0; v < 2; v++) {
            const __nv_bfloat16* __restrict__ src = v ? g_embl : g_embh;
            pa[v][0] = *(const float4*)&src[(size_t)at0 * 256 + k0];
            pa[v][1] = *(const float4*)&src[(size_t)at0 * 256 + k0 + 8];
            pa[v][2] = *(const float4*)&src[(size_t)at1 * 256 + k0];
            pa[v][3] = *(const float4*)&src[(size_t)at1 * 256 + k0 + 8];
        }
        #pragma unroll
        for (int v = 0; v < 2; v++) {
            const __nv_bfloat16* __restrict__ W = v ? g_wl[dir] : g_wh[dir];
            #pragma unroll
            for (int r = 0; r < 2; r++) {
                const int u = r * 256 + tid;
                const int nf = u >> 5, g = (u >> 2) & 7, ks = u & 3;
                const __nv_bfloat16* src =
                    W + (size_t)(col0 + nf * 8 + g) * 256 + kc * 64 + ks * 16;
                pbv[v][r][0] = *(const float4*)src;
                pbv[v][r][1] = *(const float4*)(src + 8);
            }
        }
    };
    auto stsAB = [&](int buf) {
        #pragma unroll
        for (int v = 0; v < 2; v++) {
            const u32* q0 = (const u32*)&pa[v][0];
            const u32* q1 = (const u32*)&pa[v][1];
            const u32* q2 = (const u32*)&pa[v][2];
            const u32* q3 = (const u32*)&pa[v][3];
            uint4* dst = sA + (((buf * 2 + v) * 8 + amt2) * 4 + aks) * 32 + ag * 4;
            #pragma unroll
            for (int tg = 0; tg < 4; tg++)
                dst[tg] = make_uint4(q0[tg], q2[tg], q1[tg], q3[tg]);
        }
        #pragma unroll
        for (int v = 0; v < 2; v++) {
            #pragma unroll
            for (int r = 0; r < 2; r++) {
                const int u = r * 256 + tid;
                const int nf = u >> 5, g = (u >> 2) & 7, ks = u & 3;
                const u32* q0 = (const u32*)&pbv[v][r][0];
                const u32* q1 = (const u32*)&pbv[v][r][1];
                uint4* dst = (uint4*)(sB + (((buf * 2 + v) * 16 + nf) * 4 + ks) * 32 + g * 4);
                dst[0] = make_uint4(q0[0], q1[0], q0[1], q1[1]);
                dst[1] = make_uint4(q0[2], q1[2], q0[3], q1[3]);
            }
        }
    };

    float4 D0[8] = {}, D1[8] = {};

    ldgAB(0); stsAB(0);
    __syncthreads();

    for (int kc = 0; kc < 4; kc++) {
        if (kc < 3) ldgAB(kc + 1);
        const int buf = kc & 1;

        #pragma unroll
        for (int ks = 0; ks < 4; ks++) {
            uint4 a0h = sA[(((buf * 2 + 0) * 8 + wm * 2 + 0) * 4 + ks) * 32 + lane];
            uint4 a1h = sA[(((buf * 2 + 0) * 8 + wm * 2 + 1) * 4 + ks) * 32 + lane];
            uint4 a0l = sA[(((buf * 2 + 1) * 8 + wm * 2 + 0) * 4 + ks) * 32 + lane];
            uint4 a1l = sA[(((buf * 2 + 1) * 8 + wm * 2 + 1) * 4 + ks) * 32 + lane];
            #pragma unroll
            for (int nf8 = 0; nf8 < 8; nf8++) {
                uint2 bh = sB[(((buf * 2 + 0) * 16 + wn * 8 + nf8) * 4 + ks) * 32 + lane];
                mma4(D0[nf8], a0h, bh); mma4(D1[nf8], a1h, bh);
                mma4(D0[nf8], a0l, bh); mma4(D1[nf8], a1l, bh);
            }
            #pragma unroll
            for (int nf8 = 0; nf8 < 8; nf8++) {
                uint2 bl = sB[(((buf * 2 + 1) * 16 + wn * 8 + nf8) * 4 + ks) * 32 + lane];
                mma4(D0[nf8], a0h, bl); mma4(D1[nf8], a1h, bl);
            }
        }

        if (kc < 3) stsAB((kc + 1) & 1);
        __syncthreads();
    }

    // ---- epilogue: add bias, store fp32 ----
    const int tig = lane & 3, g = lane >> 2;
    #pragma unroll
    for (int mt = 0; mt < 2; mt++) {
        const float4* Dm = mt ? D1 : D0;
        const int mt2 = wm * 2 + mt;
        #pragma unroll
        for (int half = 0; half < 2; half++) {
            const int m = mt2 * 16 + g + half * 8;
            const int b = m & 63, t = 2 * tp + (m >> 6);
            float* dst = &g_gx[dir][t][b][col0 + wn * 64 + tig * 2];
            #pragma unroll
            for (int nf8 = 0; nf8 < 8; nf8++) {
                float v0 = half ? Dm[nf8].z : Dm[nf8].x;
                float v1 = half ? Dm[nf8].w : Dm[nf8].y;
                const int nb = wn * 64 + nf8 * 8 + tig * 2;
                float2 o = make_float2(v0 + sBias[nb], v1 + sBias[nb + 1]);
                *(float2*)(dst + nf8 * 8) = o;
            }
        }
    }
}

// =================================================================================
// Kernel 2: bidirectional LSTM recurrence on HMMA.
// R9: register de-pressurize (ac[2][4] chains, inline mapa) to kill local spills;
// mbarrier cluster sync kept from R8.
// =================================================================================
#define SH_HH 0                      // u16 [2][8][264]
#define SH_HL 8448                   // u16 [2][8][264]
#define SH_Z  16896                  // f32 [2][128][10]
#define SH_AX 27136                  // uint4 [8][8][32]
#define SH_MB 59904                  // mbarrier (8 B)
#define LSTM_SMEM (59904 + 16)

__global__ __launch_bounds__(512) __cluster_dims__(8, 1, 1) void lstm_rec_kernel(
    const float* __restrict__ w_hh_f, const float* __restrict__ w_hh_b)
{
    extern __shared__ char smem[];
    u16*   sHh = (u16*)(smem + SH_HH);
    u16*   sHl = (u16*)(smem + SH_HL);
    float* sZ  = (float*)(smem + SH_Z);
    uint4* sAx = (uint4*)(smem + SH_AX);
    const u32 mb = smem_u32(smem + SH_MB);

    cg::cluster_group cluster = cg::this_cluster();
    const unsigned rank = cluster.block_rank();
    const int cid = blockIdx.x >> 3;
    const int d   = cid >> 3;
    const int b0  = (cid & 7) * 8;
    const int tid = threadIdx.x;
    const int wid = tid >> 5, lane = tid & 31;
    const int g = lane >> 2, tig = lane & 3;

    const float* __restrict__ Wg = d ? w_hh_b : w_hh_f;

    const int mtile = wid >> 1, khalf = wid & 1;
    const int m0 = mtile * 16;

    auto jglob = [&](int r) { return ((r >> 5) << 8) + (int)rank * 32 + (r & 31); };
    auto buildA = [&](int kb, int mode, u32* a) {
        const int r0 = m0 + g, r1 = m0 + g + 8;
        const int kk = kb + 2 * tig;
        const float* p0 = &Wg[(size_t)jglob(r0) * 256];
        const float* p1 = &Wg[(size_t)jglob(r1) * 256];
        float e00 = p0[kk],     e01 = p0[kk + 1];
        float e10 = p1[kk],     e11 = p1[kk + 1];
        float e02 = p0[kk + 8], e03 = p0[kk + 9];
        float e12 = p1[kk + 8], e13 = p1[kk + 9];
        if (mode) {
            e00 -= bf16_hi(e00); e01 -= bf16_hi(e01);
            e10 -= bf16_hi(e10); e11 -= bf16_hi(e11);
            e02 -= bf16_hi(e02); e03 -= bf16_hi(e03);
            e12 -= bf16_hi(e12); e13 -= bf16_hi(e13);
        }
        a[0] = pack_bf16(e00, e01);
        a[1] = pack_bf16(e10, e11);
        a[2] = pack_bf16(e02, e03);
        a[3] = pack_bf16(e12, e13);
    };

    u32 fA[16][4];
    if (khalf == 0) {
        #pragma unroll
        for (int f = 0; f < 16; f++) buildA(16 * f, 0, fA[f]);
    } else {
        #pragma unroll
        for (int f = 0; f < 16; f++) buildA(16 * f, 1, fA[f]);
        #pragma unroll
        for (int f = 0; f < 8; f++) {
            u32 a[4];
            buildA(128 + 16 * f, 0, a);
            sAx[(mtile * 8 + f) * 32 + lane] = make_uint4(a[0], a[1], a[2], a[3]);
        }
    }

    for (int i = tid; i < 8 * 264; i += 512) { sHh[i] = 0; sHl[i] = 0; }
    if (tid == 0) mbar_init(mb, 8);
    __syncthreads();
    cluster.sync();

    const int gb = (tid & 255) >> 5, gu = tid & 31;
    const int hj = (int)rank * 32 + gu;
    const u32 hh_base = smem_u32(sHh);
    const u32 mb_peer = (tid < 8) ? mapa_u32(mb, tid) : 0;

    float c = 0.0f;
    int p = 0;

    for (int s = 0; s < TT; s++) {
        const int t = d ? (TT - 1 - s) : s;

        float gxi = 0.f, gxf = 0.f, gxg = 0.f, gxo = 0.f;
        if (tid < 256) {
            const float* __restrict__ gxp = &g_gx[d][t][b0 + gb][hj];
            gxi = gxp[0]; gxf = gxp[256]; gxg = gxp[512]; gxo = gxp[768];
        }

        // ---- GEMM with 2 independent accumulator chains ----
        const u16* Hh = sHh + p * 2112 + g * 264 + 2 * tig;
        const u16* Hl = sHl + p * 2112 + g * 264 + 2 * tig;
        float ac[2][4] = {};

        if (khalf == 0) {
            #pragma unroll
            for (int f = 0; f < 16; f++) {
                u32 bb0 = *(const u32*)(Hh + 16 * f);
                u32 bb1 = *(const u32*)(Hh + 16 * f + 8);
                mma16816(ac[f & 1][0], ac[f & 1][1], ac[f & 1][2], ac[f & 1][3],
                         fA[f][0], fA[f][1], fA[f][2], fA[f][3], bb0, bb1);
            }
            #pragma unroll
            for (int f = 0; f < 8; f++) {
                u32 bb0 = *(const u32*)(Hl + 16 * f);
                u32 bb1 = *(const u32*)(Hl + 16 * f + 8);
                mma16816(ac[f & 1][0], ac[f & 1][1], ac[f & 1][2], ac[f & 1][3],
                         fA[f][0], fA[f][1], fA[f][2], fA[f][3], bb0, bb1);
            }
        } else {
            #pragma unroll
            for (int f = 0; f < 8; f++) {
                uint4 a = sAx[(mtile * 8 + f) * 32 + lane];
                u32 bb0 = *(const u32*)(Hl + 128 + 16 * f);
                u32 bb1 = *(const u32*)(Hl + 128 + 16 * f + 8);
                mma16816(ac[f & 1][0], ac[f & 1][1], ac[f & 1][2], ac[f & 1][3],
                         a.x, a.y, a.z, a.w, bb0, bb1);
            }
            #pragma unroll
            for (int f = 0; f < 16; f++) {
                u32 bb0 = *(const u32*)(Hh + 16 * f);
                u32 bb1 = *(const u32*)(Hh + 16 * f + 8);
                mma16816(ac[f & 1][0], ac[f & 1][1], ac[f & 1][2], ac[f & 1][3],
                         fA[f][0], fA[f][1], fA[f][2], fA[f][3], bb0, bb1);
            }
        }
        float d0 = ac[0][0] + ac[1][0];
        float d1 = ac[0][1] + ac[1][1];
        float d2 = ac[0][2] + ac[1][2];
        float d3 = ac[0][3] + ac[1][3];

        {
            float2* z0 = (float2*)(sZ + khalf * 1280 + (m0 + g) * 10 + 2 * tig);
            float2* z1 = (float2*)(sZ + khalf * 1280 + (m0 + g + 8) * 10 + 2 * tig);
            *z0 = make_float2(d0, d1);
            *z1 = make_float2(d2, d3);
        }
        __syncthreads();

        const int pn = p ^ 1;
        if (tid < 256) {
            float zi = sZ[gu * 10 + gb]           + sZ[1280 + gu * 10 + gb]           + gxi;
            float zf = sZ[(32 + gu) * 10 + gb]    + sZ[1280 + (32 + gu) * 10 + gb]    + gxf;
            float zg = sZ[(64 + gu) * 10 + gb]    + sZ[1280 + (64 + gu) * 10 + gb]    + gxg;
            float zo = sZ[(96 + gu) * 10 + gb]    + sZ[1280 + (96 + gu) * 10 + gb]    + gxo;
            float si = 1.0f / (1.0f + __expf(-zi));
            float sf = 1.0f / (1.0f + __expf(-zf));
            float so = 1.0f / (1.0f + __expf(-zo));
            c = sf * c + si * tanhf(zg);
            float h = so * tanhf(c);

            g_h[d][t][b0 + gb][hj] = h;

            u16 hh = __bfloat16_as_ushort(__float2bfloat16_rn(h));
            float hhf = __bfloat162float(__ushort_as_bfloat16(hh));
            u16 hl = __bfloat16_as_ushort(__float2bfloat16_rn(h - hhf));
            const u32 ah = hh_base + (u32)(pn * 2112 + gb * 264 + hj) * 2;
            const u32 al = ah + (SH_HL - SH_HH);
            #pragma unroll
            for (int pr = 0; pr < 8; pr++) {
                st_cluster_u16(mapa_u32(ah, pr), hh);
                st_cluster_u16(mapa_u32(al, pr), hl);
            }
        }
        __syncthreads();
        if (tid < 8) mbar_arrive_cluster(mb_peer);
        mbar_wait_acq(mb, (u32)(s & 1));
        p = pn;
    }
    cluster.sync();
}

// =================================================================================
// Kernel 3: scores = concat(h_f,h_b) @ w_fc^T + b_fc (FFMA2 GEMM, unchanged).
// =================================================================================
__global__ __launch_bounds__(256) void scores_kernel(
    const float* __restrict__ w_fc, const float* __restrict__ b_fc)
{
    __shared__ __align__(16) float As[16 * 64];
    __shared__ __align__(16) float Bs[16 * 32];

    const int b   = blockIdx.x;
    const int t0  = blockIdx.y * 64;
    const int tid = threadIdx.x;
    const int lm  = tid >> 2, kq = (tid & 3) << 2;
    const int ty  = tid >> 4, tx = tid & 15;

    u64 acc[2][2] = {};

    for (int k0 = 0; k0 < 512; k0 += 16) {
        const int dir = k0 >> 8, dk = k0 & 255;
        float4 av = *(const float4*)&g_h[dir][t0 + lm][b][dk + kq];
        As[(kq + 0) * 64 + lm] = av.x; As[(kq + 1) * 64 + lm] = av.y;
        As[(kq + 2) * 64 + lm] = av.z; As[(kq + 3) * 64 + lm] = av.w;
        for (int q = tid; q < 512; q += 256) {
            int kk = q >> 5, n = q & 31;
            Bs[kk * 32 + n] = w_fc[n * 512 + k0 + kk];
        }
        __syncthreads();

        #pragma unroll
        for (int kk = 0; kk < 16; kk++) {
            ulonglong2 ap = *(const ulonglong2*)&As[kk * 64 + ty * 4];
            float2 bv = *(const float2*)&Bs[kk * 32 + tx * 2];
            u64 b0 = dup2(bv.x), b1 = dup2(bv.y);
            ffma2(acc[0][0], ap.x, b0); ffma2(acc[0][1], ap.x, b1);
            ffma2(acc[1][0], ap.y, b0); ffma2(acc[1][1], ap.y, b1);
        }
        __syncthreads();
    }

    #pragma unroll
    for (int cc = 0; cc < 2; cc++) {
        const int col = tx * 2 + cc;
        const float bias = b_fc[col];
        #pragma unroll
        for (int rp = 0; rp < 2; rp++) {
            F2U v; v.u = acc[rp][cc];
            g_scores[b][t0 + ty * 4 + rp * 2 + 0][col] = v.f.x + bias;
            g_scores[b][t0 + ty * 4 + rp * 2 + 1][col] = v.f.y + bias;
        }
    }
}

// =================================================================================
// Kernel 4: CRF (unchanged).
// =================================================================================
__global__ __launch_bounds__(32) void crf_kernel(
    const int* __restrict__ tags, const int* __restrict__ mask,
    const float* __restrict__ trans)
{
    __shared__ float sT[1024];
    __shared__ float sE[1024];
    __shared__ __align__(16) float sA[32];
    const int b = blockIdx.x;
    const int j = threadIdx.x;

    for (int i = j; i < 1024; i += 32) {
        float tv = trans[i];
        sT[i] = tv;
        sE[i] = __expf(tv);
    }
    __syncwarp();

    float Ereg[32];
    #pragma unroll
    for (int i = 0; i < 32; i++) Ereg[i] = sE[i * 32 + j];

    int len = 0;
    for (int t = j; t < TT; t += 32) len += mask[b * TT + t];
    #pragma unroll
    for (int o = 16; o; o >>= 1) len += __shfl_xor_sync(0xffffffffu, len, o);

    const int* __restrict__ tg = tags + b * TT;
    float body = 0.0f;
    for (int t = 1 + j; t < len; t += 32) {
        int tp = tg[t - 1], tc = tg[t];
        body += sT[tp * 32 + tc] + g_scores[b][t][tc];
    }
    #pragma unroll
    for (int o = 16; o; o >>= 1) body += __shfl_xor_sync(0xffffffffu, body, o);
    const int t0 = tg[0];
    const float truep = sT[30 * 32 + t0] + g_scores[b][0][t0] + body
                      + sT[tg[len - 1] * 32 + 31];

    float alpha = sT[30 * 32 + j] + g_scores[b][0][j];
    for (int t = 1; t < len; t++) {
        float aref = __shfl_sync(0xffffffffu, alpha, 1);
        float e = __expf(alpha - aref);
        sA[j] = e;
        __syncwarp();
        float s0 = 0.f, s1 = 0.f, s2 = 0.f, s3 = 0.f;
        const float4* A4 = (const float4*)sA;
        #pragma unroll
        for (int i = 0; i < 8; i++) {
            float4 ev = A4[i];
            s0 = fmaf(ev.x, Ereg[4 * i + 0], s0);
            s1 = fmaf(ev.y, Ereg[4 * i + 1], s1);
            s2 = fmaf(ev.z, Ereg[4 * i + 2], s2);
            s3 = fmaf(ev.w, Ereg[4 * i + 3], s3);
        }
        float s = (s0 + s1) + (s2 + s3);
        alpha = g_scores[b][t][j] + aref + __logf(s);
        __syncwarp();
    }

    float v = alpha + sT[j * 32 + 31];
    float m = v;
    #pragma unroll
    for (int o = 16; o; o >>= 1) m = fmaxf(m, __shfl_xor_sync(0xffffffffu, m, o));
    float e = __expf(v - m);
    #pragma unroll
    for (int o = 16; o; o >>= 1) e += __shfl_xor_sync(0xffffffffu, e, o);
    if (j == 0) g_loss[b] = (m + __logf(e)) - truep;
}

__global__ void finalize_kernel(float* __restrict__ out)
{
    if (threadIdx.x == 0) {
        float s = 0.0f;
        for (int b = 0; b < BB; b++) s += g_loss[b];
        out[0] = s;
    }
}

// =================================================================================
extern "C" void kernel_launch(void* const* d_in, const int* in_sizes, int n_in,
                              void* d_out, int out_size)
{
    const int*   x      = (const int*)  d_in[0];
    const int*   tags   = (const int*)  d_in[1];
    const int*   mask   = (const int*)  d_in[2];
    const float* emb    = (const float*)d_in[3];
    const float* w_ih_f = (const float*)d_in[4];
    const float* w_hh_f = (const float*)d_in[5];
    const float* b_f    = (const float*)d_in[6];
    const float* w_ih_b = (const float*)d_in[7];
    const float* w_hh_b = (const float*)d_in[8];
    const float* b_b    = (const float*)d_in[9];
    const float* w_fc   = (const float*)d_in[10];
    const float* b_fc   = (const float*)d_in[11];
    const float* trans  = (const float*)d_in[12];
    float* out = (float*)d_out;

    cudaFuncSetAttribute(lstm_rec_kernel,
                         cudaFuncAttributeMaxDynamicSharedMemorySize, LSTM_SMEM);
    cudaFuncSetAttribute(hmma_proj_kernel,
                         cudaFuncAttributeMaxDynamicSharedMemorySize, PJ_SMEM);

    __nv_bfloat16 *p_eh, *p_el, *p_wh, *p_wl;
    cudaGetSymbolAddress((void**)&p_eh, g_embh);
    cudaGetSymbolAddress((void**)&p_el, g_embl);
    cudaGetSymbolAddress((void**)&p_wh, g_wh);
    cudaGetSymbolAddress((void**)&p_wl, g_wl);

    split3_kernel<<<32048, 256>>>(emb, w_ih_f, w_ih_b, p_eh, p_el, p_wh, p_wl);

    hmma_proj_kernel<<<dim3(16, 256), 256, PJ_SMEM>>>(x, b_f, b_b);
    lstm_rec_kernel<<<128, 512, LSTM_SMEM>>>(w_hh_f, w_hh_b);
    scores_kernel<<<dim3(64, 8), 256>>>(w_fc, b_fc);
    crf_kernel<<<64, 32>>>(tags, mask, trans);
    finalize_kernel<<<1, 32>>>(out);
}